// round 7
// baseline (speedup 1.0000x reference)
#include <cuda_runtime.h>
#include <cuda_fp16.h>
#include <cstdint>

#define SQ   2048
#define EDIM 1024
#define FDIM 4096
#define NH   8
#define HD   128
#define NL   4
#define VOC  32000
#define HDW  (NH * HD)     // 1024

typedef __half hf;

// ---------------------------------------------------------------------------
// static scratch: fp16 hi/lo planes (weights converted for ALL layers upfront)
// ---------------------------------------------------------------------------
__device__ hf g_hh [SQ * EDIM];
__device__ hf g_hl [SQ * EDIM];
__device__ hf g_hfh[SQ * FDIM];
__device__ hf g_hfl[SQ * FDIM];
__device__ hf g_qh [SQ * HDW];
__device__ hf g_ql [SQ * HDW];
__device__ hf g_kh [SQ * HDW];
__device__ hf g_kl [SQ * HDW];
__device__ hf g_vh [SQ * HDW];
__device__ hf g_vl [SQ * HDW];
__device__ hf g_oh [SQ * HDW];
__device__ hf g_ol [SQ * HDW];
__device__ hf g_ffth[NL * FDIM * EDIM];
__device__ hf g_fftl[NL * FDIM * EDIM];
__device__ hf g_qth [NL * HDW * FDIM];
__device__ hf g_qtl [NL * HDW * FDIM];
__device__ hf g_kth [NL * HDW * FDIM];
__device__ hf g_ktl [NL * HDW * FDIM];
__device__ hf g_vth [NL * HDW * FDIM];
__device__ hf g_vtl [NL * HDW * FDIM];
__device__ hf g_oth [NL * EDIM * HDW];
__device__ hf g_otl [NL * EDIM * HDW];
__device__ hf g_eth [VOC * EDIM];
__device__ hf g_etl [VOC * EDIM];

// ---------------------------------------------------------------------------
// helpers
// ---------------------------------------------------------------------------
__device__ __forceinline__ uint32_t smem_u32(const void* p) {
    return (uint32_t)__cvta_generic_to_shared(p);
}
__device__ __forceinline__ void cp_async16(uint32_t dst, const void* src) {
    asm volatile("cp.async.cg.shared.global [%0], [%1], 16;\n" :: "r"(dst), "l"(src));
}
__device__ __forceinline__ void cp_commit() {
    asm volatile("cp.async.commit_group;\n");
}
template <int N>
__device__ __forceinline__ void cp_wait() {
    asm volatile("cp.async.wait_group %0;\n" :: "n"(N));
}
__device__ __forceinline__ void mma16(float* c, const uint32_t* a, uint32_t b0, uint32_t b1) {
    asm volatile(
        "mma.sync.aligned.m16n8k16.row.col.f32.f16.f16.f32 "
        "{%0,%1,%2,%3}, {%4,%5,%6,%7}, {%8,%9}, {%0,%1,%2,%3};\n"
        : "+f"(c[0]), "+f"(c[1]), "+f"(c[2]), "+f"(c[3])
        : "r"(a[0]), "r"(a[1]), "r"(a[2]), "r"(a[3]), "r"(b0), "r"(b1));
}
__device__ __forceinline__ void ldsm4(uint32_t* r, uint32_t a) {
    asm volatile("ldmatrix.sync.aligned.m8n8.x4.shared.b16 {%0,%1,%2,%3}, [%4];"
                 : "=r"(r[0]), "=r"(r[1]), "=r"(r[2]), "=r"(r[3]) : "r"(a));
}
__device__ __forceinline__ void ldsm4t(uint32_t* r, uint32_t a) {
    asm volatile("ldmatrix.sync.aligned.m8n8.x4.trans.shared.b16 {%0,%1,%2,%3}, [%4];"
                 : "=r"(r[0]), "=r"(r[1]), "=r"(r[2]), "=r"(r[3]) : "r"(a));
}
__device__ __forceinline__ uint32_t pk(hf a, hf b) {
    return ((uint32_t)__half_as_ushort(b) << 16) | __half_as_ushort(a);
}
__device__ __forceinline__ void split2(float f0, float f1, uint32_t& h, uint32_t& l) {
    hf h0 = __float2half_rn(f0), h1 = __float2half_rn(f1);
    hf l0 = __float2half_rn(f0 - __half2float(h0));
    hf l1 = __float2half_rn(f1 - __half2float(h1));
    h = pk(h0, h1);
    l = pk(l0, l1);
}

// ---------------------------------------------------------------------------
// fp16 3-term GEMM: C[M,N] = op(A @ B^T); A[M,K], B[N,K] hi/lo half planes.
// CTA 128 x BNT, BK=32, 8 warps (2 x 4), warp tile 64 x (BNT/4), 3-stage.
// smem rows: 32 halfs (64B) at 80B pitch (conflict-free ldmatrix + stores).
// ---------------------------------------------------------------------------
template <int RELU, int SPLIT, int BNT>
__device__ __forceinline__ void hgemm_body(
    const hf* __restrict__ Ah_, const hf* __restrict__ Al_,
    const hf* __restrict__ Bh_, const hf* __restrict__ Bl_,
    float* __restrict__ C, hf* __restrict__ Ch, hf* __restrict__ Cl,
    int M, int N, int K, int m0, int n0)
{
    constexpr int PLA = 128 * 80;            // A plane bytes
    constexpr int PLB = BNT * 80;            // B plane bytes
    constexpr int STG = 2 * PLA + 2 * PLB;   // stage bytes
    constexpr int WN  = BNT / 4;             // warp n extent (32 or 64)
    constexpr int PR  = WN / 16;             // 16-row B blocks per warp (2 or 4)
    constexpr int NT  = WN / 8;              // n8 tiles per warp (4 or 8)
    constexpr int BU  = BNT / 64;            // B cp.async chunks per plane per thread

    extern __shared__ char smraw[];
    uint32_t sb = smem_u32(smraw);
    const int tid = threadIdx.x, lane = tid & 31, warp = tid >> 5;
    const int wr = warp >> 2, wc = warp & 3;
    const int lq = lane >> 2, lr = lane & 3;

    const hf* srcA[2] = { Ah_ + (size_t)m0 * K, Al_ + (size_t)m0 * K };
    const hf* srcB[2] = { Bh_ + (size_t)n0 * K, Bl_ + (size_t)n0 * K };
    const int crow = tid >> 2, cc = tid & 3;

    auto issue = [&](int st, int k0) {
        uint32_t base = sb + (uint32_t)st * STG;
#pragma unroll
        for (int pl = 0; pl < 2; pl++)
#pragma unroll
            for (int u = 0; u < 2; u++) {
                int row = crow + u * 64;
                cp_async16(base + pl * PLA + row * 80 + cc * 16,
                           srcA[pl] + (size_t)row * K + k0 + cc * 8);
            }
#pragma unroll
        for (int pl = 0; pl < 2; pl++)
#pragma unroll
            for (int u = 0; u < BU; u++) {
                int row = crow + u * 64;
                cp_async16(base + 2 * PLA + pl * PLB + row * 80 + cc * 16,
                           srcB[pl] + (size_t)row * K + k0 + cc * 8);
            }
        cp_commit();
    };

    const uint32_t a_off = (uint32_t)(wr * 64 + (lane & 15)) * 80 +
                           (uint32_t)(((lane >> 4) & 1) * 16);
    const uint32_t b_off = (uint32_t)(wc * WN + ((lane >> 4) & 1) * 8 + (lane & 7)) * 80 +
                           (uint32_t)(((lane >> 3) & 1) * 16);

    float acc[4][NT][4];
#pragma unroll
    for (int i = 0; i < 4; i++)
#pragma unroll
        for (int j = 0; j < NT; j++)
#pragma unroll
            for (int q = 0; q < 4; q++) acc[i][j][q] = 0.f;

    const int KT = K >> 5;
    issue(0, 0);
    issue(1, 32);

    for (int kt = 0; kt < KT; kt++) {
        if (kt + 1 < KT) cp_wait<1>(); else cp_wait<0>();
        __syncthreads();
        if (kt + 2 < KT) issue((kt + 2) % 3, (kt + 2) * 32);
        else cp_commit();

        uint32_t stg = sb + (uint32_t)(kt % 3) * STG;
#pragma unroll
        for (int ks = 0; ks < 2; ks++) {
            uint32_t ah[4][4], al[4][4];
#pragma unroll
            for (int mt = 0; mt < 4; mt++) {
                uint32_t ad = stg + a_off + mt * (16 * 80) + ks * 32;
                ldsm4(ah[mt], ad);
                ldsm4(al[mt], ad + PLA);
            }
            uint32_t bh[PR][4], bl[PR][4];
#pragma unroll
            for (int pr = 0; pr < PR; pr++) {
                uint32_t bd = stg + 2 * PLA + b_off + pr * (16 * 80) + ks * 32;
                ldsm4(bh[pr], bd);
                ldsm4(bl[pr], bd + PLB);
            }
#pragma unroll
            for (int mt = 0; mt < 4; mt++)
#pragma unroll
                for (int pr = 0; pr < PR; pr++)
#pragma unroll
                    for (int oc = 0; oc < 2; oc++) {
                        int nt = pr * 2 + oc;
                        mma16(acc[mt][nt], ah[mt], bh[pr][2*oc], bh[pr][2*oc+1]);
                        mma16(acc[mt][nt], ah[mt], bl[pr][2*oc], bl[pr][2*oc+1]);
                        mma16(acc[mt][nt], al[mt], bh[pr][2*oc], bh[pr][2*oc+1]);
                    }
        }
    }

    // epilogue
#pragma unroll
    for (int mt = 0; mt < 4; mt++) {
        int r0 = m0 + wr * 64 + mt * 16 + lq;
#pragma unroll
        for (int nt = 0; nt < NT; nt++) {
            int col = n0 + wc * WN + nt * 8 + lr * 2;
            float v0 = acc[mt][nt][0], v1 = acc[mt][nt][1];
            float v2 = acc[mt][nt][2], v3 = acc[mt][nt][3];
            if (RELU) {
                v0 = fmaxf(v0, 0.f); v1 = fmaxf(v1, 0.f);
                v2 = fmaxf(v2, 0.f); v3 = fmaxf(v3, 0.f);
            }
            if (SPLIT == 0) {
                *(float2*)(C + (size_t)r0 * N + col) = make_float2(v0, v1);
                *(float2*)(C + (size_t)(r0 + 8) * N + col) = make_float2(v2, v3);
            } else {
                uint32_t h, l;
                split2(v0, v1, h, l);
                *(uint32_t*)(Ch + (size_t)r0 * N + col) = h;
                *(uint32_t*)(Cl + (size_t)r0 * N + col) = l;
                split2(v2, v3, h, l);
                *(uint32_t*)(Ch + (size_t)(r0 + 8) * N + col) = h;
                *(uint32_t*)(Cl + (size_t)(r0 + 8) * N + col) = l;
            }
        }
    }
}

template <int RELU, int SPLIT, int BNT>
__global__ __launch_bounds__(256, 1)
void hgemm_kernel(const hf* __restrict__ Ah, const hf* __restrict__ Al,
                  const hf* __restrict__ Bh, const hf* __restrict__ Bl,
                  float* __restrict__ C, hf* __restrict__ Ch, hf* __restrict__ Cl,
                  int M, int N, int K) {
    hgemm_body<RELU, SPLIT, BNT>(Ah, Al, Bh, Bl, C, Ch, Cl, M, N, K,
                                 blockIdx.y * 128, blockIdx.x * BNT);
}

__global__ __launch_bounds__(256, 1)
void hgemm_qkv(const hf* __restrict__ Ah, const hf* __restrict__ Al,
               const hf* __restrict__ B0h, const hf* __restrict__ B0l,
               const hf* __restrict__ B1h, const hf* __restrict__ B1l,
               const hf* __restrict__ B2h, const hf* __restrict__ B2l,
               hf* __restrict__ C0h, hf* __restrict__ C0l,
               hf* __restrict__ C1h, hf* __restrict__ C1l,
               hf* __restrict__ C2h, hf* __restrict__ C2l,
               int M, int N, int K) {
    const hf* Bh = (blockIdx.z == 0) ? B0h : (blockIdx.z == 1) ? B1h : B2h;
    const hf* Bl = (blockIdx.z == 0) ? B0l : (blockIdx.z == 1) ? B1l : B2l;
    hf* Ch = (blockIdx.z == 0) ? C0h : (blockIdx.z == 1) ? C1h : C2h;
    hf* Cl = (blockIdx.z == 0) ? C0l : (blockIdx.z == 1) ? C1l : C2l;
    hgemm_body<0, 1, 256>(Ah, Al, Bh, Bl, nullptr, Ch, Cl, M, N, K,
                          blockIdx.y * 128, blockIdx.x * 256);
}

#define GS256 (3 * (2 * 128 * 80 + 2 * 256 * 80))   // 184320
#define GS128 (3 * (2 * 128 * 80 + 2 * 128 * 80))   // 122880

// ---------------------------------------------------------------------------
// ALL weight transposes + fp16 hi/lo splits for all layers in ONE launch.
// grid: (17408, NL). Tiles 32x32. Per layer: ff 4096 | q 4096 | k 4096 |
// v 4096 | o 1024 tiles.
// ---------------------------------------------------------------------------
__global__ __launch_bounds__(256)
void wconv_all(const float* __restrict__ ffw, const float* __restrict__ qw,
               const float* __restrict__ kw, const float* __restrict__ vw,
               const float* __restrict__ ow,
               hf* __restrict__ ffth, hf* __restrict__ fftl,
               hf* __restrict__ qth,  hf* __restrict__ qtl,
               hf* __restrict__ kth,  hf* __restrict__ ktl,
               hf* __restrict__ vth,  hf* __restrict__ vtl,
               hf* __restrict__ oth,  hf* __restrict__ otl) {
    __shared__ float t[32][33];
    int layer = blockIdx.y;
    int b = blockIdx.x;

    const float* W; hf* Th; hf* Tl; int R, Cc, tt;
    if (b < 4096)      { W = ffw + (size_t)layer * EDIM * FDIM;
                         Th = ffth + (size_t)layer * FDIM * EDIM;
                         Tl = fftl + (size_t)layer * FDIM * EDIM;
                         R = EDIM; Cc = FDIM; tt = b; }
    else if (b < 8192) { W = qw + (size_t)layer * FDIM * HDW;
                         Th = qth + (size_t)layer * HDW * FDIM;
                         Tl = qtl + (size_t)layer * HDW * FDIM;
                         R = FDIM; Cc = HDW; tt = b - 4096; }
    else if (b < 12288){ W = kw + (size_t)layer * FDIM * HDW;
                         Th = kth + (size_t)layer * HDW * FDIM;
                         Tl = ktl + (size_t)layer * HDW * FDIM;
                         R = FDIM; Cc = HDW; tt = b - 8192; }
    else if (b < 16384){ W = vw + (size_t)layer * FDIM * HDW;
                         Th = vth + (size_t)layer * HDW * FDIM;
                         Tl = vtl + (size_t)layer * HDW * FDIM;
                         R = FDIM; Cc = HDW; tt = b - 12288; }
    else               { W = ow + (size_t)layer * HDW * EDIM;
                         Th = oth + (size_t)layer * EDIM * HDW;
                         Tl = otl + (size_t)layer * EDIM * HDW;
                         R = HDW; Cc = EDIM; tt = b - 16384; }

    int ntx = Cc / 32;
    int c0 = (tt % ntx) * 32, r0 = (tt / ntx) * 32;
    int tx = threadIdx.x & 31, ty = threadIdx.x >> 5;
#pragma unroll
    for (int i = 0; i < 32; i += 8)
        t[ty + i][tx] = W[(size_t)(r0 + ty + i) * Cc + c0 + tx];
    __syncthreads();
#pragma unroll
    for (int i = 0; i < 32; i += 8) {
        float v = t[tx][ty + i];
        hf h = __float2half_rn(v);
        hf l = __float2half_rn(v - __half2float(h));
        size_t o = (size_t)(c0 + ty + i) * R + r0 + tx;
        Th[o] = h;
        Tl[o] = l;
    }
}

// straight split (embedding as logits-B; already [N,K])
__global__ __launch_bounds__(256)
void conv_split(const float* __restrict__ X, hf* __restrict__ Xh,
                hf* __restrict__ Xl, int n4) {
    int i = blockIdx.x * 256 + threadIdx.x;
    if (i >= n4) return;
    float4 v = ((const float4*)X)[i];
    uint32_t h0, l0, h1, l1;
    split2(v.x, v.y, h0, l0);
    split2(v.z, v.w, h1, l1);
    ((uint2*)Xh)[i] = make_uint2(h0, h1);
    ((uint2*)Xl)[i] = make_uint2(l0, l1);
}

__global__ void embed_kernel(const int* __restrict__ x,
                             const float* __restrict__ emb,
                             hf* __restrict__ hh, hf* __restrict__ hl) {
    int s = blockIdx.x;
    int tok = x[s];
    const float4* src = (const float4*)(emb + (size_t)tok * EDIM);
    uint2* dh = (uint2*)(hh + (size_t)s * EDIM);
    uint2* dl = (uint2*)(hl + (size_t)s * EDIM);
    for (int i = threadIdx.x; i < EDIM / 4; i += blockDim.x) {
        float4 v = src[i];
        uint32_t h0, l0, h1, l1;
        split2(v.x, v.y, h0, l0);
        split2(v.z, v.w, h1, l1);
        dh[i] = make_uint2(h0, h1);
        dl[i] = make_uint2(l0, l1);
    }
}

// ---------------------------------------------------------------------------
// Flash attention with fp16 mma, 3-term splits for QK and PV.
// CTA: 128 queries x 1 head; 8 warps x 16 rows. Key tiles of 64, 3-stage.
// ---------------------------------------------------------------------------
#define KP    272
#define APL   (64 * KP)
#define ASTG4 (4 * APL)
#define ATT_SMEM (3 * ASTG4)

__global__ __launch_bounds__(256)
void attn_mma(const hf* __restrict__ Qh, const hf* __restrict__ Ql,
              const hf* __restrict__ Kh, const hf* __restrict__ Kl,
              const hf* __restrict__ Vh, const hf* __restrict__ Vl,
              hf* __restrict__ Oh, hf* __restrict__ Ol) {
    extern __shared__ char smraw[];
    uint32_t sb = smem_u32(smraw);
    const int tid = threadIdx.x, lane = tid & 31, warp = tid >> 5;
    const int lq = lane >> 2, lr = lane & 3;
    const int qb = blockIdx.x, head = blockIdx.y;

    {
        const hf* qsrc[2] = { Qh, Ql };
#pragma unroll
        for (int pl = 0; pl < 2; pl++)
#pragma unroll
            for (int u = 0; u < 8; u++) {
                int id = tid + u * 256;
                int row = id >> 4, c = id & 15;
                cp_async16(sb + pl * (2 * APL) + row * KP + c * 16,
                           qsrc[pl] + (size_t)(qb * 128 + row) * HDW + head * HD + c * 8);
            }
        cp_commit();
        cp_wait<0>();
        __syncthreads();
    }
    uint32_t qfh[8][4], qfl[8][4];
    {
        uint32_t q_off = (uint32_t)(warp * 16 + (lane & 15)) * KP +
                         (uint32_t)(((lane >> 4) & 1) * 16);
#pragma unroll
        for (int kc = 0; kc < 8; kc++) {
            ldsm4(qfh[kc], sb + q_off + kc * 32);
            ldsm4(qfl[kc], sb + 2 * APL + q_off + kc * 32);
        }
    }
    __syncthreads();

    const hf* kvsrc[4] = { Kh, Kl, Vh, Vl };
    auto loadKV = [&](int t, int st) {
        uint32_t base = sb + (uint32_t)st * ASTG4;
#pragma unroll
        for (int pl = 0; pl < 4; pl++)
#pragma unroll
            for (int u = 0; u < 4; u++) {
                int id = tid + u * 256;
                int row = id >> 4, c = id & 15;
                cp_async16(base + pl * APL + row * KP + c * 16,
                           kvsrc[pl] + (size_t)(t * 64 + row) * HDW + head * HD + c * 8);
            }
        cp_commit();
    };

    float o_acc[16][4];
#pragma unroll
    for (int i = 0; i < 16; i++)
#pragma unroll
        for (int j = 0; j < 4; j++) o_acc[i][j] = 0.f;
    float mrun[2] = { -1e30f, -1e30f };
    float lrun[2] = { 0.f, 0.f };

    const int NT = 2 * qb + 2;
    loadKV(0, 0);
    if (NT > 1) loadKV(1, 1);

    const uint32_t k_off = (uint32_t)(((lane >> 4) & 1) * 8 + (lane & 7)) * KP +
                           (uint32_t)(((lane >> 3) & 1) * 16);
    const uint32_t v_off = (uint32_t)(((lane >> 3) & 1) * 8 + (lane & 7)) * KP +
                           (uint32_t)(((lane >> 4) & 1) * 16);

    for (int t = 0; t < NT; t++) {
        if (t + 1 < NT) cp_wait<1>(); else cp_wait<0>();
        __syncthreads();
        if (t + 2 < NT) loadKV(t + 2, (t + 2) % 3);
        else cp_commit();

        uint32_t stg = sb + (uint32_t)(t % 3) * ASTG4;

        float s_acc[8][4];
#pragma unroll
        for (int i = 0; i < 8; i++)
#pragma unroll
            for (int j = 0; j < 4; j++) s_acc[i][j] = 0.f;

#pragma unroll
        for (int kc = 0; kc < 8; kc++) {
            uint32_t kbh[4][4], kbl[4][4];
#pragma unroll
            for (int pr = 0; pr < 4; pr++) {
                uint32_t ad = stg + k_off + pr * (16 * KP) + kc * 32;
                ldsm4(kbh[pr], ad);
                ldsm4(kbl[pr], ad + APL);
            }
#pragma unroll
            for (int pr = 0; pr < 4; pr++)
#pragma unroll
                for (int oc = 0; oc < 2; oc++) {
                    int nt = pr * 2 + oc;
                    mma16(s_acc[nt], qfh[kc], kbh[pr][2*oc], kbh[pr][2*oc+1]);
                    mma16(s_acc[nt], qfh[kc], kbl[pr][2*oc], kbl[pr][2*oc+1]);
                    mma16(s_acc[nt], qfl[kc], kbh[pr][2*oc], kbh[pr][2*oc+1]);
                }
        }

        if (t >= 2 * qb) {
            int rbase = qb * 128 + warp * 16 + lq;
#pragma unroll
            for (int nt = 0; nt < 8; nt++)
#pragma unroll
                for (int rr = 0; rr < 4; rr++) {
                    int col = t * 64 + nt * 8 + 2 * lr + (rr & 1);
                    int row = rbase + (rr >> 1) * 8;
                    if (col > row) s_acc[nt][rr] = -1e30f;
                }
        }

#pragma unroll
        for (int h = 0; h < 2; h++) {
            float mloc = -1e30f;
#pragma unroll
            for (int nt = 0; nt < 8; nt++) {
                mloc = fmaxf(mloc, s_acc[nt][2*h]);
                mloc = fmaxf(mloc, s_acc[nt][2*h+1]);
            }
            mloc = fmaxf(mloc, __shfl_xor_sync(0xffffffffu, mloc, 1));
            mloc = fmaxf(mloc, __shfl_xor_sync(0xffffffffu, mloc, 2));
            float mnew = fmaxf(mrun[h], mloc);
            float corr = __expf(mrun[h] - mnew);
            mrun[h] = mnew;
            float ps = 0.f;
#pragma unroll
            for (int nt = 0; nt < 8; nt++) {
                float p0 = __expf(s_acc[nt][2*h]   - mnew);
                float p1 = __expf(s_acc[nt][2*h+1] - mnew);
                s_acc[nt][2*h] = p0;
                s_acc[nt][2*h+1] = p1;
                ps += p0 + p1;
            }
            ps += __shfl_xor_sync(0xffffffffu, ps, 1);
            ps += __shfl_xor_sync(0xffffffffu, ps, 2);
            lrun[h] = lrun[h] * corr + ps;
#pragma unroll
            for (int nt = 0; nt < 16; nt++) {
                o_acc[nt][2*h]   *= corr;
                o_acc[nt][2*h+1] *= corr;
            }
        }

#pragma unroll
        for (int kc2 = 0; kc2 < 4; kc2++) {
            uint32_t ph[4], pl[4];
            split2(s_acc[2*kc2][0],   s_acc[2*kc2][1],   ph[0], pl[0]);
            split2(s_acc[2*kc2][2],   s_acc[2*kc2][3],   ph[1], pl[1]);
            split2(s_acc[2*kc2+1][0], s_acc[2*kc2+1][1], ph[2], pl[2]);
            split2(s_acc[2*kc2+1][2], s_acc[2*kc2+1][3], ph[3], pl[3]);
#pragma unroll
            for (int dp = 0; dp < 8; dp++) {
                uint32_t vbh[4], vbl[4];
                uint32_t ad = stg + 2 * APL + v_off + kc2 * (16 * KP) + dp * 32;
                ldsm4t(vbh, ad);
                ldsm4t(vbl, ad + APL);
#pragma unroll
                for (int oc = 0; oc < 2; oc++) {
                    int nt = dp * 2 + oc;
                    mma16(o_acc[nt], ph, vbh[2*oc], vbh[2*oc+1]);
                    mma16(o_acc[nt], ph, vbl[2*oc], vbl[2*oc+1]);
                    mma16(o_acc[nt], pl, vbh[2*oc], vbh[2*oc+1]);
                }
            }
        }
    }

    float inv0 = 1.f / lrun[0], inv1 = 1.f / lrun[1];
    int r0 = qb * 128 + warp * 16 + lq;
#pragma unroll
    for (int nt = 0; nt < 16; nt++) {
        int col = head * HD + nt * 8 + 2 * lr;
        uint32_t h, l;
        split2(o_acc[nt][0] * inv0, o_acc[nt][1] * inv0, h, l);
        *(uint32_t*)(Oh + (size_t)r0 * HDW + col) = h;
        *(uint32_t*)(Ol + (size_t)r0 * HDW + col) = l;
        split2(o_acc[nt][2] * inv1, o_acc[nt][3] * inv1, h, l);
        *(uint32_t*)(Oh + (size_t)(r0 + 8) * HDW + col) = h;
        *(uint32_t*)(Ol + (size_t)(r0 + 8) * HDW + col) = l;
    }
}

// ---------------------------------------------------------------------------
extern "C" void kernel_launch(void* const* d_in, const int* in_sizes, int n_in,
                              void* d_out, int out_size) {
    const int*   x   = (const int*)d_in[0];
    const float* emb = (const float*)d_in[1];
    const float* ffw = (const float*)d_in[2];
    const float* qw  = (const float*)d_in[3];
    const float* kw  = (const float*)d_in[4];
    const float* vw  = (const float*)d_in[5];
    const float* ow  = (const float*)d_in[6];
    float* out = (float*)d_out;

    hf *hh, *hl, *hfh, *hfl, *qh, *ql, *kh, *kl, *vh, *vl, *oh, *ol;
    hf *ffth, *fftl, *qth, *qtl, *kth, *ktl, *vth, *vtl, *oth, *otl, *eth, *etl;
    cudaGetSymbolAddress((void**)&hh,  g_hh);  cudaGetSymbolAddress((void**)&hl,  g_hl);
    cudaGetSymbolAddress((void**)&hfh, g_hfh); cudaGetSymbolAddress((void**)&hfl, g_hfl);
    cudaGetSymbolAddress((void**)&qh,  g_qh);  cudaGetSymbolAddress((void**)&ql,  g_ql);
    cudaGetSymbolAddress((void**)&kh,  g_kh);  cudaGetSymbolAddress((void**)&kl,  g_kl);
    cudaGetSymbolAddress((void**)&vh,  g_vh);  cudaGetSymbolAddress((void**)&vl,  g_vl);
    cudaGetSymbolAddress((void**)&oh,  g_oh);  cudaGetSymbolAddress((void**)&ol,  g_ol);
    cudaGetSymbolAddress((void**)&ffth, g_ffth); cudaGetSymbolAddress((void**)&fftl, g_fftl);
    cudaGetSymbolAddress((void**)&qth,  g_qth);  cudaGetSymbolAddress((void**)&qtl,  g_qtl);
    cudaGetSymbolAddress((void**)&kth,  g_kth);  cudaGetSymbolAddress((void**)&ktl,  g_ktl);
    cudaGetSymbolAddress((void**)&vth,  g_vth);  cudaGetSymbolAddress((void**)&vtl,  g_vtl);
    cudaGetSymbolAddress((void**)&oth,  g_oth);  cudaGetSymbolAddress((void**)&otl,  g_otl);
    cudaGetSymbolAddress((void**)&eth,  g_eth);  cudaGetSymbolAddress((void**)&etl,  g_etl);

    cudaFuncSetAttribute(attn_mma,
                         cudaFuncAttributeMaxDynamicSharedMemorySize, ATT_SMEM);
    cudaFuncSetAttribute(hgemm_kernel<1, 1, 256>,
                         cudaFuncAttributeMaxDynamicSharedMemorySize, GS256);
    cudaFuncSetAttribute(hgemm_kernel<0, 1, 128>,
                         cudaFuncAttributeMaxDynamicSharedMemorySize, GS128);
    cudaFuncSetAttribute(hgemm_kernel<0, 0, 256>,
                         cudaFuncAttributeMaxDynamicSharedMemorySize, GS256);
    cudaFuncSetAttribute(hgemm_qkv,
                         cudaFuncAttributeMaxDynamicSharedMemorySize, GS256);

    // launches 1-3: all conversions
    embed_kernel<<<SQ, 256>>>(x, emb, hh, hl);
    conv_split<<<(VOC * EDIM / 4 + 255) / 256, 256>>>(emb, eth, etl, VOC * EDIM / 4);
    wconv_all<<<dim3(17408, NL), 256>>>(ffw, qw, kw, vw, ow,
                                        ffth, fftl, qth, qtl, kth, ktl,
                                        vth, vtl, oth, otl);

    for (int i = 0; i < NL; i++) {
        hf* ffthi = ffth + (size_t)i * FDIM * EDIM;
        hf* fftli = fftl + (size_t)i * FDIM * EDIM;
        hf* qthi  = qth  + (size_t)i * HDW * FDIM;
        hf* qtli  = qtl  + (size_t)i * HDW * FDIM;
        hf* kthi  = kth  + (size_t)i * HDW * FDIM;
        hf* ktli  = ktl  + (size_t)i * HDW * FDIM;
        hf* vthi  = vth  + (size_t)i * HDW * FDIM;
        hf* vtli  = vtl  + (size_t)i * HDW * FDIM;
        hf* othi  = oth  + (size_t)i * EDIM * HDW;
        hf* otli  = otl  + (size_t)i * EDIM * HDW;

        // hf = relu(h @ ff_w): [2048,1024] @ [1024,4096]
        hgemm_kernel<1, 1, 256><<<dim3(FDIM / 256, SQ / 128), 256, GS256>>>(
            hh, hl, ffthi, fftli, nullptr, hfh, hfl, SQ, FDIM, EDIM);

        // q,k,v = hf @ w: [2048,4096] @ [4096,1024]
        hgemm_qkv<<<dim3(HDW / 256, SQ / 128, 3), 256, GS256>>>(
            hfh, hfl, qthi, qtli, kthi, ktli, vthi, vtli,
            qh, ql, kh, kl, vh, vl, SQ, HDW, FDIM);

        // attention
        attn_mma<<<dim3(SQ / 128, NH), 256, ATT_SMEM>>>(
            qh, ql, kh, kl, vh, vl, oh, ol);

        // h = o @ o_w: [2048,1024] @ [1024,1024]  (128-wide tiles: 128 CTAs)
        hgemm_kernel<0, 1, 128><<<dim3(EDIM / 128, SQ / 128), 256, GS128>>>(
            oh, ol, othi, otli, nullptr, hh, hl, SQ, EDIM, HDW);
    }

    // logits = h @ emb^T: [2048,1024] @ [32000,1024]^T
    hgemm_kernel<0, 0, 256><<<dim3(VOC / 256, SQ / 128), 256, GS256>>>(
        hh, hl, eth, etl, out, nullptr, nullptr, SQ, VOC, EDIM);
}

// round 8
// speedup vs baseline: 1.1111x; 1.1111x over previous
#include <cuda_runtime.h>
#include <cuda_fp16.h>
#include <cstdint>

#define SQ   2048
#define EDIM 1024
#define FDIM 4096
#define NH   8
#define HD   128
#define NL   4
#define VOC  32000
#define HDW  (NH * HD)     // 1024

typedef __half hf;

// ---------------------------------------------------------------------------
// static scratch: fp16 hi/lo planes (weights converted for ALL layers upfront)
// ---------------------------------------------------------------------------
__device__ hf g_hh [SQ * EDIM];
__device__ hf g_hl [SQ * EDIM];
__device__ hf g_hfh[SQ * FDIM];
__device__ hf g_hfl[SQ * FDIM];
__device__ hf g_qh [SQ * HDW];
__device__ hf g_ql [SQ * HDW];
__device__ hf g_kh [SQ * HDW];
__device__ hf g_kl [SQ * HDW];
__device__ hf g_vh [SQ * HDW];
__device__ hf g_vl [SQ * HDW];
__device__ hf g_oh [SQ * HDW];
__device__ hf g_ol [SQ * HDW];
__device__ hf g_ffth[NL * FDIM * EDIM];
__device__ hf g_fftl[NL * FDIM * EDIM];
__device__ hf g_qth [NL * HDW * FDIM];
__device__ hf g_qtl [NL * HDW * FDIM];
__device__ hf g_kth [NL * HDW * FDIM];
__device__ hf g_ktl [NL * HDW * FDIM];
__device__ hf g_vth [NL * HDW * FDIM];
__device__ hf g_vtl [NL * HDW * FDIM];
__device__ hf g_oth [NL * EDIM * HDW];
__device__ hf g_otl [NL * EDIM * HDW];
__device__ hf g_eth [VOC * EDIM];
__device__ hf g_etl [VOC * EDIM];

// ---------------------------------------------------------------------------
// helpers
// ---------------------------------------------------------------------------
__device__ __forceinline__ uint32_t smem_u32(const void* p) {
    return (uint32_t)__cvta_generic_to_shared(p);
}
__device__ __forceinline__ void cp_async16(uint32_t dst, const void* src) {
    asm volatile("cp.async.cg.shared.global [%0], [%1], 16;\n" :: "r"(dst), "l"(src));
}
__device__ __forceinline__ void cp_commit() {
    asm volatile("cp.async.commit_group;\n");
}
template <int N>
__device__ __forceinline__ void cp_wait() {
    asm volatile("cp.async.wait_group %0;\n" :: "n"(N));
}
__device__ __forceinline__ void mma16(float* c, const uint32_t* a, uint32_t b0, uint32_t b1) {
    asm volatile(
        "mma.sync.aligned.m16n8k16.row.col.f32.f16.f16.f32 "
        "{%0,%1,%2,%3}, {%4,%5,%6,%7}, {%8,%9}, {%0,%1,%2,%3};\n"
        : "+f"(c[0]), "+f"(c[1]), "+f"(c[2]), "+f"(c[3])
        : "r"(a[0]), "r"(a[1]), "r"(a[2]), "r"(a[3]), "r"(b0), "r"(b1));
}
__device__ __forceinline__ void ldsm4(uint32_t* r, uint32_t a) {
    asm volatile("ldmatrix.sync.aligned.m8n8.x4.shared.b16 {%0,%1,%2,%3}, [%4];"
                 : "=r"(r[0]), "=r"(r[1]), "=r"(r[2]), "=r"(r[3]) : "r"(a));
}
__device__ __forceinline__ void ldsm4t(uint32_t* r, uint32_t a) {
    asm volatile("ldmatrix.sync.aligned.m8n8.x4.trans.shared.b16 {%0,%1,%2,%3}, [%4];"
                 : "=r"(r[0]), "=r"(r[1]), "=r"(r[2]), "=r"(r[3]) : "r"(a));
}
__device__ __forceinline__ uint32_t pk(hf a, hf b) {
    return ((uint32_t)__half_as_ushort(b) << 16) | __half_as_ushort(a);
}
__device__ __forceinline__ void split2(float f0, float f1, uint32_t& h, uint32_t& l) {
    hf h0 = __float2half_rn(f0), h1 = __float2half_rn(f1);
    hf l0 = __float2half_rn(f0 - __half2float(h0));
    hf l1 = __float2half_rn(f1 - __half2float(h1));
    h = pk(h0, h1);
    l = pk(l0, l1);
}

// ---------------------------------------------------------------------------
// fp16 split GEMM: C[M,N] = op(A @ B^T); A[M,K], B[N,K] hi/lo half planes.
// CTA BMT x BNT, BK=32, 8 warps (2 x 4), warp tile (BMT/2) x (BNT/4), 3-stage.
// TERMS=3: AhBh + AhBl + AlBh; TERMS=2: AhBh + AlBh (Bl plane never loaded).
// smem rows: 32 halfs (64B) at 80B pitch.
// ---------------------------------------------------------------------------
template <int RELU, int SPLIT, int BMT, int BNT, int TERMS>
__device__ __forceinline__ void hgemm_body(
    const hf* __restrict__ Ah_, const hf* __restrict__ Al_,
    const hf* __restrict__ Bh_, const hf* __restrict__ Bl_,
    float* __restrict__ C, hf* __restrict__ Ch, hf* __restrict__ Cl,
    int M, int N, int K, int m0, int n0)
{
    constexpr int PLA = BMT * 80;
    constexpr int PLB = BNT * 80;
    constexpr int NBP = (TERMS == 3) ? 2 : 1;          // B planes
    constexpr int STG = 2 * PLA + NBP * PLB;
    constexpr int WM  = BMT / 2;
    constexpr int WN  = BNT / 4;
    constexpr int MT  = WM / 16;
    constexpr int PR  = WN / 16;
    constexpr int NT  = WN / 8;
    constexpr int ACH = 2 * BMT * 4;                   // A 16B chunks / stage
    constexpr int BCH = NBP * BNT * 4;
    constexpr int AU  = ACH / 256;
    constexpr int BU  = BCH / 256;

    extern __shared__ char smraw[];
    uint32_t sb = smem_u32(smraw);
    const int tid = threadIdx.x, lane = tid & 31, warp = tid >> 5;
    const int wr = warp >> 2, wc = warp & 3;
    const int lq = lane >> 2, lr = lane & 3;

    const hf* srcA[2] = { Ah_ + (size_t)m0 * K, Al_ + (size_t)m0 * K };
    const hf* srcB[2] = { Bh_ + (size_t)n0 * K, Bl_ ? Bl_ + (size_t)n0 * K : Bh_ };

    auto issue = [&](int st, int k0) {
        uint32_t base = sb + (uint32_t)st * STG;
#pragma unroll
        for (int u = 0; u < AU; u++) {
            int id = tid + u * 256;
            int pl = id / (BMT * 4), rem = id % (BMT * 4);
            int row = rem >> 2, c = rem & 3;
            cp_async16(base + pl * PLA + row * 80 + c * 16,
                       srcA[pl] + (size_t)row * K + k0 + c * 8);
        }
#pragma unroll
        for (int u = 0; u < BU; u++) {
            int id = tid + u * 256;
            int pl = id / (BNT * 4), rem = id % (BNT * 4);
            int row = rem >> 2, c = rem & 3;
            cp_async16(base + 2 * PLA + pl * PLB + row * 80 + c * 16,
                       srcB[pl] + (size_t)row * K + k0 + c * 8);
        }
        cp_commit();
    };

    const uint32_t a_off = (uint32_t)(wr * WM + (lane & 15)) * 80 +
                           (uint32_t)(((lane >> 4) & 1) * 16);
    const uint32_t b_off = (uint32_t)(wc * WN + ((lane >> 4) & 1) * 8 + (lane & 7)) * 80 +
                           (uint32_t)(((lane >> 3) & 1) * 16);

    float acc[MT][NT][4];
#pragma unroll
    for (int i = 0; i < MT; i++)
#pragma unroll
        for (int j = 0; j < NT; j++)
#pragma unroll
            for (int q = 0; q < 4; q++) acc[i][j][q] = 0.f;

    const int KT = K >> 5;
    issue(0, 0);
    issue(1, 32);

    for (int kt = 0; kt < KT; kt++) {
        if (kt + 1 < KT) cp_wait<1>(); else cp_wait<0>();
        __syncthreads();
        if (kt + 2 < KT) issue((kt + 2) % 3, (kt + 2) * 32);
        else cp_commit();

        uint32_t stg = sb + (uint32_t)(kt % 3) * STG;
#pragma unroll
        for (int ks = 0; ks < 2; ks++) {
            uint32_t ah[MT][4], al[MT][4];
#pragma unroll
            for (int mt = 0; mt < MT; mt++) {
                uint32_t ad = stg + a_off + mt * (16 * 80) + ks * 32;
                ldsm4(ah[mt], ad);
                ldsm4(al[mt], ad + PLA);
            }
            uint32_t bh[PR][4], bl[PR][4];
#pragma unroll
            for (int pr = 0; pr < PR; pr++) {
                uint32_t bd = stg + 2 * PLA + b_off + pr * (16 * 80) + ks * 32;
                ldsm4(bh[pr], bd);
                if (TERMS == 3) ldsm4(bl[pr], bd + PLB);
            }
#pragma unroll
            for (int mt = 0; mt < MT; mt++)
#pragma unroll
                for (int pr = 0; pr < PR; pr++)
#pragma unroll
                    for (int oc = 0; oc < 2; oc++) {
                        int nt = pr * 2 + oc;
                        mma16(acc[mt][nt], ah[mt], bh[pr][2*oc], bh[pr][2*oc+1]);
                        if (TERMS == 3)
                            mma16(acc[mt][nt], ah[mt], bl[pr][2*oc], bl[pr][2*oc+1]);
                        mma16(acc[mt][nt], al[mt], bh[pr][2*oc], bh[pr][2*oc+1]);
                    }
        }
    }

    // epilogue
#pragma unroll
    for (int mt = 0; mt < MT; mt++) {
        int r0 = m0 + wr * WM + mt * 16 + lq;
#pragma unroll
        for (int nt = 0; nt < NT; nt++) {
            int col = n0 + wc * WN + nt * 8 + lr * 2;
            float v0 = acc[mt][nt][0], v1 = acc[mt][nt][1];
            float v2 = acc[mt][nt][2], v3 = acc[mt][nt][3];
            if (RELU) {
                v0 = fmaxf(v0, 0.f); v1 = fmaxf(v1, 0.f);
                v2 = fmaxf(v2, 0.f); v3 = fmaxf(v3, 0.f);
            }
            if (SPLIT == 0) {
                *(float2*)(C + (size_t)r0 * N + col) = make_float2(v0, v1);
                *(float2*)(C + (size_t)(r0 + 8) * N + col) = make_float2(v2, v3);
            } else {
                uint32_t h, l;
                split2(v0, v1, h, l);
                *(uint32_t*)(Ch + (size_t)r0 * N + col) = h;
                *(uint32_t*)(Cl + (size_t)r0 * N + col) = l;
                split2(v2, v3, h, l);
                *(uint32_t*)(Ch + (size_t)(r0 + 8) * N + col) = h;
                *(uint32_t*)(Cl + (size_t)(r0 + 8) * N + col) = l;
            }
        }
    }
}

template <int RELU, int SPLIT, int BMT, int BNT, int TERMS, int NSWAP>
__global__ __launch_bounds__(256, 1)
void hgemm_kernel(const hf* __restrict__ Ah, const hf* __restrict__ Al,
                  const hf* __restrict__ Bh, const hf* __restrict__ Bl,
                  float* __restrict__ C, hf* __restrict__ Ch, hf* __restrict__ Cl,
                  int M, int N, int K) {
    int m0 = (NSWAP ? blockIdx.x : blockIdx.y) * BMT;
    int n0 = (NSWAP ? blockIdx.y : blockIdx.x) * BNT;
    hgemm_body<RELU, SPLIT, BMT, BNT, TERMS>(Ah, Al, Bh, Bl, C, Ch, Cl,
                                             M, N, K, m0, n0);
}

__global__ __launch_bounds__(256, 1)
void hgemm_qkv(const hf* __restrict__ Ah, const hf* __restrict__ Al,
               const hf* __restrict__ B0h, const hf* __restrict__ B0l,
               const hf* __restrict__ B1h, const hf* __restrict__ B1l,
               const hf* __restrict__ B2h, const hf* __restrict__ B2l,
               hf* __restrict__ C0h, hf* __restrict__ C0l,
               hf* __restrict__ C1h, hf* __restrict__ C1l,
               hf* __restrict__ C2h, hf* __restrict__ C2l,
               int M, int N, int K) {
    const hf* Bh = (blockIdx.z == 0) ? B0h : (blockIdx.z == 1) ? B1h : B2h;
    const hf* Bl = (blockIdx.z == 0) ? B0l : (blockIdx.z == 1) ? B1l : B2l;
    hf* Ch = (blockIdx.z == 0) ? C0h : (blockIdx.z == 1) ? C1h : C2h;
    hf* Cl = (blockIdx.z == 0) ? C0l : (blockIdx.z == 1) ? C1l : C2l;
    hgemm_body<0, 1, 64, 256, 3>(Ah, Al, Bh, Bl, nullptr, Ch, Cl, M, N, K,
                                 blockIdx.y * 64, blockIdx.x * 256);
}

#define GS_FF   (3 * (2 * 128 * 80 + 2 * 256 * 80))   // 184320
#define GS_QKV  (3 * (2 *  64 * 80 + 2 * 256 * 80))   // 153600
#define GS_OP   (3 * (2 * 128 * 80 + 2 * 128 * 80))   // 122880
#define GS_LG   (3 * (2 * 128 * 80 + 1 * 256 * 80))   // 122880

// ---------------------------------------------------------------------------
// ALL weight transposes + fp16 hi/lo splits for all layers in ONE launch.
// ---------------------------------------------------------------------------
__global__ __launch_bounds__(256)
void wconv_all(const float* __restrict__ ffw, const float* __restrict__ qw,
               const float* __restrict__ kw, const float* __restrict__ vw,
               const float* __restrict__ ow,
               hf* __restrict__ ffth, hf* __restrict__ fftl,
               hf* __restrict__ qth,  hf* __restrict__ qtl,
               hf* __restrict__ kth,  hf* __restrict__ ktl,
               hf* __restrict__ vth,  hf* __restrict__ vtl,
               hf* __restrict__ oth,  hf* __restrict__ otl) {
    __shared__ float t[32][33];
    int layer = blockIdx.y;
    int b = blockIdx.x;

    const float* W; hf* Th; hf* Tl; int R, Cc, tt;
    if (b < 4096)      { W = ffw + (size_t)layer * EDIM * FDIM;
                         Th = ffth + (size_t)layer * FDIM * EDIM;
                         Tl = fftl + (size_t)layer * FDIM * EDIM;
                         R = EDIM; Cc = FDIM; tt = b; }
    else if (b < 8192) { W = qw + (size_t)layer * FDIM * HDW;
                         Th = qth + (size_t)layer * HDW * FDIM;
                         Tl = qtl + (size_t)layer * HDW * FDIM;
                         R = FDIM; Cc = HDW; tt = b - 4096; }
    else if (b < 12288){ W = kw + (size_t)layer * FDIM * HDW;
                         Th = kth + (size_t)layer * HDW * FDIM;
                         Tl = ktl + (size_t)layer * HDW * FDIM;
                         R = FDIM; Cc = HDW; tt = b - 8192; }
    else if (b < 16384){ W = vw + (size_t)layer * FDIM * HDW;
                         Th = vth + (size_t)layer * HDW * FDIM;
                         Tl = vtl + (size_t)layer * HDW * FDIM;
                         R = FDIM; Cc = HDW; tt = b - 12288; }
    else               { W = ow + (size_t)layer * HDW * EDIM;
                         Th = oth + (size_t)layer * EDIM * HDW;
                         Tl = otl + (size_t)layer * EDIM * HDW;
                         R = HDW; Cc = EDIM; tt = b - 16384; }

    int ntx = Cc / 32;
    int c0 = (tt % ntx) * 32, r0 = (tt / ntx) * 32;
    int tx = threadIdx.x & 31, ty = threadIdx.x >> 5;
#pragma unroll
    for (int i = 0; i < 32; i += 8)
        t[ty + i][tx] = W[(size_t)(r0 + ty + i) * Cc + c0 + tx];
    __syncthreads();
#pragma unroll
    for (int i = 0; i < 32; i += 8) {
        float v = t[tx][ty + i];
        hf h = __float2half_rn(v);
        hf l = __float2half_rn(v - __half2float(h));
        size_t o = (size_t)(c0 + ty + i) * R + r0 + tx;
        Th[o] = h;
        Tl[o] = l;
    }
}

__global__ __launch_bounds__(256)
void conv_split(const float* __restrict__ X, hf* __restrict__ Xh,
                hf* __restrict__ Xl, int n4) {
    int i = blockIdx.x * 256 + threadIdx.x;
    if (i >= n4) return;
    float4 v = ((const float4*)X)[i];
    uint32_t h0, l0, h1, l1;
    split2(v.x, v.y, h0, l0);
    split2(v.z, v.w, h1, l1);
    ((uint2*)Xh)[i] = make_uint2(h0, h1);
    ((uint2*)Xl)[i] = make_uint2(l0, l1);
}

__global__ void embed_kernel(const int* __restrict__ x,
                             const float* __restrict__ emb,
                             hf* __restrict__ hh, hf* __restrict__ hl) {
    int s = blockIdx.x;
    int tok = x[s];
    const float4* src = (const float4*)(emb + (size_t)tok * EDIM);
    uint2* dh = (uint2*)(hh + (size_t)s * EDIM);
    uint2* dl = (uint2*)(hl + (size_t)s * EDIM);
    for (int i = threadIdx.x; i < EDIM / 4; i += blockDim.x) {
        float4 v = src[i];
        uint32_t h0, l0, h1, l1;
        split2(v.x, v.y, h0, l0);
        split2(v.z, v.w, h1, l1);
        dh[i] = make_uint2(h0, h1);
        dl[i] = make_uint2(l0, l1);
    }
}

// ---------------------------------------------------------------------------
// Flash attention with fp16 mma, 3-term splits for QK and PV.
// ---------------------------------------------------------------------------
#define KP    272
#define APL   (64 * KP)
#define ASTG4 (4 * APL)
#define ATT_SMEM (3 * ASTG4)

__global__ __launch_bounds__(256)
void attn_mma(const hf* __restrict__ Qh, const hf* __restrict__ Ql,
              const hf* __restrict__ Kh, const hf* __restrict__ Kl,
              const hf* __restrict__ Vh, const hf* __restrict__ Vl,
              hf* __restrict__ Oh, hf* __restrict__ Ol) {
    extern __shared__ char smraw[];
    uint32_t sb = smem_u32(smraw);
    const int tid = threadIdx.x, lane = tid & 31, warp = tid >> 5;
    const int lq = lane >> 2, lr = lane & 3;
    const int qb = blockIdx.x, head = blockIdx.y;

    {
        const hf* qsrc[2] = { Qh, Ql };
#pragma unroll
        for (int pl = 0; pl < 2; pl++)
#pragma unroll
            for (int u = 0; u < 8; u++) {
                int id = tid + u * 256;
                int row = id >> 4, c = id & 15;
                cp_async16(sb + pl * (2 * APL) + row * KP + c * 16,
                           qsrc[pl] + (size_t)(qb * 128 + row) * HDW + head * HD + c * 8);
            }
        cp_commit();
        cp_wait<0>();
        __syncthreads();
    }
    uint32_t qfh[8][4], qfl[8][4];
    {
        uint32_t q_off = (uint32_t)(warp * 16 + (lane & 15)) * KP +
                         (uint32_t)(((lane >> 4) & 1) * 16);
#pragma unroll
        for (int kc = 0; kc < 8; kc++) {
            ldsm4(qfh[kc], sb + q_off + kc * 32);
            ldsm4(qfl[kc], sb + 2 * APL + q_off + kc * 32);
        }
    }
    __syncthreads();

    const hf* kvsrc[4] = { Kh, Kl, Vh, Vl };
    auto loadKV = [&](int t, int st) {
        uint32_t base = sb + (uint32_t)st * ASTG4;
#pragma unroll
        for (int pl = 0; pl < 4; pl++)
#pragma unroll
            for (int u = 0; u < 4; u++) {
                int id = tid + u * 256;
                int row = id >> 4, c = id & 15;
                cp_async16(base + pl * APL + row * KP + c * 16,
                           kvsrc[pl] + (size_t)(t * 64 + row) * HDW + head * HD + c * 8);
            }
        cp_commit();
    };

    float o_acc[16][4];
#pragma unroll
    for (int i = 0; i < 16; i++)
#pragma unroll
        for (int j = 0; j < 4; j++) o_acc[i][j] = 0.f;
    float mrun[2] = { -1e30f, -1e30f };
    float lrun[2] = { 0.f, 0.f };

    const int NT = 2 * qb + 2;
    loadKV(0, 0);
    if (NT > 1) loadKV(1, 1);

    const uint32_t k_off = (uint32_t)(((lane >> 4) & 1) * 8 + (lane & 7)) * KP +
                           (uint32_t)(((lane >> 3) & 1) * 16);
    const uint32_t v_off = (uint32_t)(((lane >> 3) & 1) * 8 + (lane & 7)) * KP +
                           (uint32_t)(((lane >> 4) & 1) * 16);

    for (int t = 0; t < NT; t++) {
        if (t + 1 < NT) cp_wait<1>(); else cp_wait<0>();
        __syncthreads();
        if (t + 2 < NT) loadKV(t + 2, (t + 2) % 3);
        else cp_commit();

        uint32_t stg = sb + (uint32_t)(t % 3) * ASTG4;

        float s_acc[8][4];
#pragma unroll
        for (int i = 0; i < 8; i++)
#pragma unroll
            for (int j = 0; j < 4; j++) s_acc[i][j] = 0.f;

#pragma unroll
        for (int kc = 0; kc < 8; kc++) {
            uint32_t kbh[4][4], kbl[4][4];
#pragma unroll
            for (int pr = 0; pr < 4; pr++) {
                uint32_t ad = stg + k_off + pr * (16 * KP) + kc * 32;
                ldsm4(kbh[pr], ad);
                ldsm4(kbl[pr], ad + APL);
            }
#pragma unroll
            for (int pr = 0; pr < 4; pr++)
#pragma unroll
                for (int oc = 0; oc < 2; oc++) {
                    int nt = pr * 2 + oc;
                    mma16(s_acc[nt], qfh[kc], kbh[pr][2*oc], kbh[pr][2*oc+1]);
                    mma16(s_acc[nt], qfh[kc], kbl[pr][2*oc], kbl[pr][2*oc+1]);
                    mma16(s_acc[nt], qfl[kc], kbh[pr][2*oc], kbh[pr][2*oc+1]);
                }
        }

        if (t >= 2 * qb) {
            int rbase = qb * 128 + warp * 16 + lq;
#pragma unroll
            for (int nt = 0; nt < 8; nt++)
#pragma unroll
                for (int rr = 0; rr < 4; rr++) {
                    int col = t * 64 + nt * 8 + 2 * lr + (rr & 1);
                    int row = rbase + (rr >> 1) * 8;
                    if (col > row) s_acc[nt][rr] = -1e30f;
                }
        }

#pragma unroll
        for (int h = 0; h < 2; h++) {
            float mloc = -1e30f;
#pragma unroll
            for (int nt = 0; nt < 8; nt++) {
                mloc = fmaxf(mloc, s_acc[nt][2*h]);
                mloc = fmaxf(mloc, s_acc[nt][2*h+1]);
            }
            mloc = fmaxf(mloc, __shfl_xor_sync(0xffffffffu, mloc, 1));
            mloc = fmaxf(mloc, __shfl_xor_sync(0xffffffffu, mloc, 2));
            float mnew = fmaxf(mrun[h], mloc);
            float corr = __expf(mrun[h] - mnew);
            mrun[h] = mnew;
            float ps = 0.f;
#pragma unroll
            for (int nt = 0; nt < 8; nt++) {
                float p0 = __expf(s_acc[nt][2*h]   - mnew);
                float p1 = __expf(s_acc[nt][2*h+1] - mnew);
                s_acc[nt][2*h] = p0;
                s_acc[nt][2*h+1] = p1;
                ps += p0 + p1;
            }
            ps += __shfl_xor_sync(0xffffffffu, ps, 1);
            ps += __shfl_xor_sync(0xffffffffu, ps, 2);
            lrun[h] = lrun[h] * corr + ps;
#pragma unroll
            for (int nt = 0; nt < 16; nt++) {
                o_acc[nt][2*h]   *= corr;
                o_acc[nt][2*h+1] *= corr;
            }
        }

#pragma unroll
        for (int kc2 = 0; kc2 < 4; kc2++) {
            uint32_t ph[4], pl[4];
            split2(s_acc[2*kc2][0],   s_acc[2*kc2][1],   ph[0], pl[0]);
            split2(s_acc[2*kc2][2],   s_acc[2*kc2][3],   ph[1], pl[1]);
            split2(s_acc[2*kc2+1][0], s_acc[2*kc2+1][1], ph[2], pl[2]);
            split2(s_acc[2*kc2+1][2], s_acc[2*kc2+1][3], ph[3], pl[3]);
#pragma unroll
            for (int dp = 0; dp < 8; dp++) {
                uint32_t vbh[4], vbl[4];
                uint32_t ad = stg + 2 * APL + v_off + kc2 * (16 * KP) + dp * 32;
                ldsm4t(vbh, ad);
                ldsm4t(vbl, ad + APL);
#pragma unroll
                for (int oc = 0; oc < 2; oc++) {
                    int nt = dp * 2 + oc;
                    mma16(o_acc[nt], ph, vbh[2*oc], vbh[2*oc+1]);
                    mma16(o_acc[nt], ph, vbl[2*oc], vbl[2*oc+1]);
                    mma16(o_acc[nt], pl, vbh[2*oc], vbh[2*oc+1]);
                }
            }
        }
    }

    float inv0 = 1.f / lrun[0], inv1 = 1.f / lrun[1];
    int r0 = qb * 128 + warp * 16 + lq;
#pragma unroll
    for (int nt = 0; nt < 16; nt++) {
        int col = head * HD + nt * 8 + 2 * lr;
        uint32_t h, l;
        split2(o_acc[nt][0] * inv0, o_acc[nt][1] * inv0, h, l);
        *(uint32_t*)(Oh + (size_t)r0 * HDW + col) = h;
        *(uint32_t*)(Ol + (size_t)r0 * HDW + col) = l;
        split2(o_acc[nt][2] * inv1, o_acc[nt][3] * inv1, h, l);
        *(uint32_t*)(Oh + (size_t)(r0 + 8) * HDW + col) = h;
        *(uint32_t*)(Ol + (size_t)(r0 + 8) * HDW + col) = l;
    }
}

// ---------------------------------------------------------------------------
extern "C" void kernel_launch(void* const* d_in, const int* in_sizes, int n_in,
                              void* d_out, int out_size) {
    const int*   x   = (const int*)d_in[0];
    const float* emb = (const float*)d_in[1];
    const float* ffw = (const float*)d_in[2];
    const float* qw  = (const float*)d_in[3];
    const float* kw  = (const float*)d_in[4];
    const float* vw  = (const float*)d_in[5];
    const float* ow  = (const float*)d_in[6];
    float* out = (float*)d_out;

    hf *hh, *hl, *hfh, *hfl, *qh, *ql, *kh, *kl, *vh, *vl, *oh, *ol;
    hf *ffth, *fftl, *qth, *qtl, *kth, *ktl, *vth, *vtl, *oth, *otl, *eth, *etl;
    cudaGetSymbolAddress((void**)&hh,  g_hh);  cudaGetSymbolAddress((void**)&hl,  g_hl);
    cudaGetSymbolAddress((void**)&hfh, g_hfh); cudaGetSymbolAddress((void**)&hfl, g_hfl);
    cudaGetSymbolAddress((void**)&qh,  g_qh);  cudaGetSymbolAddress((void**)&ql,  g_ql);
    cudaGetSymbolAddress((void**)&kh,  g_kh);  cudaGetSymbolAddress((void**)&kl,  g_kl);
    cudaGetSymbolAddress((void**)&vh,  g_vh);  cudaGetSymbolAddress((void**)&vl,  g_vl);
    cudaGetSymbolAddress((void**)&oh,  g_oh);  cudaGetSymbolAddress((void**)&ol,  g_ol);
    cudaGetSymbolAddress((void**)&ffth, g_ffth); cudaGetSymbolAddress((void**)&fftl, g_fftl);
    cudaGetSymbolAddress((void**)&qth,  g_qth);  cudaGetSymbolAddress((void**)&qtl,  g_qtl);
    cudaGetSymbolAddress((void**)&kth,  g_kth);  cudaGetSymbolAddress((void**)&ktl,  g_ktl);
    cudaGetSymbolAddress((void**)&vth,  g_vth);  cudaGetSymbolAddress((void**)&vtl,  g_vtl);
    cudaGetSymbolAddress((void**)&oth,  g_oth);  cudaGetSymbolAddress((void**)&otl,  g_otl);
    cudaGetSymbolAddress((void**)&eth,  g_eth);  cudaGetSymbolAddress((void**)&etl,  g_etl);

    cudaFuncSetAttribute(attn_mma,
                         cudaFuncAttributeMaxDynamicSharedMemorySize, ATT_SMEM);
    cudaFuncSetAttribute(hgemm_kernel<1, 1, 128, 256, 3, 0>,
                         cudaFuncAttributeMaxDynamicSharedMemorySize, GS_FF);
    cudaFuncSetAttribute(hgemm_kernel<0, 1, 128, 128, 3, 0>,
                         cudaFuncAttributeMaxDynamicSharedMemorySize, GS_OP);
    cudaFuncSetAttribute(hgemm_kernel<0, 0, 128, 256, 2, 1>,
                         cudaFuncAttributeMaxDynamicSharedMemorySize, GS_LG);
    cudaFuncSetAttribute(hgemm_qkv,
                         cudaFuncAttributeMaxDynamicSharedMemorySize, GS_QKV);

    embed_kernel<<<SQ, 256>>>(x, emb, hh, hl);
    conv_split<<<(VOC * EDIM / 4 + 255) / 256, 256>>>(emb, eth, etl, VOC * EDIM / 4);
    wconv_all<<<dim3(17408, NL), 256>>>(ffw, qw, kw, vw, ow,
                                        ffth, fftl, qth, qtl, kth, ktl,
                                        vth, vtl, oth, otl);

    for (int i = 0; i < NL; i++) {
        hf* ffthi = ffth + (size_t)i * FDIM * EDIM;
        hf* fftli = fftl + (size_t)i * FDIM * EDIM;
        hf* qthi  = qth  + (size_t)i * HDW * FDIM;
        hf* qtli  = qtl  + (size_t)i * HDW * FDIM;
        hf* kthi  = kth  + (size_t)i * HDW * FDIM;
        hf* ktli  = ktl  + (size_t)i * HDW * FDIM;
        hf* vthi  = vth  + (size_t)i * HDW * FDIM;
        hf* vtli  = vtl  + (size_t)i * HDW * FDIM;
        hf* othi  = oth  + (size_t)i * EDIM * HDW;
        hf* otli  = otl  + (size_t)i * EDIM * HDW;

        // hf = relu(h @ ff_w): [2048,1024] @ [1024,4096], 3-term
        hgemm_kernel<1, 1, 128, 256, 3, 0><<<dim3(FDIM / 256, SQ / 128), 256, GS_FF>>>(
            hh, hl, ffthi, fftli, nullptr, hfh, hfl, SQ, FDIM, EDIM);

        // q,k,v = hf @ w: [2048,4096] @ [4096,1024], 64x256 tiles (384 CTAs)
        hgemm_qkv<<<dim3(HDW / 256, SQ / 64, 3), 256, GS_QKV>>>(
            hfh, hfl, qthi, qtli, kthi, ktli, vthi, vtli,
            qh, ql, kh, kl, vh, vl, SQ, HDW, FDIM);

        // attention
        attn_mma<<<dim3(SQ / 128, NH), 256, ATT_SMEM>>>(
            qh, ql, kh, kl, vh, vl, oh, ol);

        // h = o @ o_w: [2048,1024] @ [1024,1024]
        hgemm_kernel<0, 1, 128, 128, 3, 0><<<dim3(EDIM / 128, SQ / 128), 256, GS_OP>>>(
            oh, ol, othi, otli, nullptr, hh, hl, SQ, EDIM, HDW);
    }

    // logits = h @ emb^T: [2048,1024] @ [32000,1024]^T
    // 2-term (Bl never loaded), grid swapped (m fastest) for B-tile L2 reuse
    hgemm_kernel<0, 0, 128, 256, 2, 1><<<dim3(SQ / 128, VOC / 256), 256, GS_LG>>>(
        hh, hl, eth, etl, out, nullptr, nullptr, SQ, VOC, EDIM);
}

// round 11
// speedup vs baseline: 1.2452x; 1.1207x over previous
#include <cuda_runtime.h>
#include <cuda_fp16.h>
#include <cstdint>

#define SQ   2048
#define EDIM 1024
#define FDIM 4096
#define NH   8
#define HD   128
#define NL   4
#define VOC  32000
#define HDW  (NH * HD)     // 1024

typedef __half hf;

// ---------------------------------------------------------------------------
// static scratch: fp16 hi/lo planes
// ---------------------------------------------------------------------------
__device__ hf g_hh [SQ * EDIM];
__device__ hf g_hl [SQ * EDIM];
__device__ hf g_hfh[SQ * FDIM];
__device__ hf g_hfl[SQ * FDIM];
__device__ hf g_qh [SQ * HDW];
__device__ hf g_ql [SQ * HDW];
__device__ hf g_kh [SQ * HDW];
__device__ hf g_kl [SQ * HDW];
__device__ hf g_vh [SQ * HDW];
__device__ hf g_vl [SQ * HDW];
__device__ hf g_oh [SQ * HDW];
__device__ hf g_ol [SQ * HDW];
__device__ hf g_ffth[NL * FDIM * EDIM];
__device__ hf g_fftl[NL * FDIM * EDIM];
__device__ hf g_qth [NL * HDW * FDIM];
__device__ hf g_qtl [NL * HDW * FDIM];
__device__ hf g_kth [NL * HDW * FDIM];
__device__ hf g_ktl [NL * HDW * FDIM];
__device__ hf g_vth [NL * HDW * FDIM];
__device__ hf g_vtl [NL * HDW * FDIM];
__device__ hf g_oth [NL * EDIM * HDW];
__device__ hf g_otl [NL * EDIM * HDW];
__device__ hf g_eth [VOC * EDIM];
__device__ hf g_etl [VOC * EDIM];

// ---------------------------------------------------------------------------
// helpers
// ---------------------------------------------------------------------------
__device__ __forceinline__ uint32_t smem_u32(const void* p) {
    return (uint32_t)__cvta_generic_to_shared(p);
}
__device__ __forceinline__ void cp_async16(uint32_t dst, const void* src) {
    asm volatile("cp.async.cg.shared.global [%0], [%1], 16;\n" :: "r"(dst), "l"(src));
}
__device__ __forceinline__ void cp_commit() {
    asm volatile("cp.async.commit_group;\n");
}
template <int N>
__device__ __forceinline__ void cp_wait() {
    asm volatile("cp.async.wait_group %0;\n" :: "n"(N));
}
__device__ __forceinline__ void mma16(float* c, const uint32_t* a, uint32_t b0, uint32_t b1) {
    asm volatile(
        "mma.sync.aligned.m16n8k16.row.col.f32.f16.f16.f32 "
        "{%0,%1,%2,%3}, {%4,%5,%6,%7}, {%8,%9}, {%0,%1,%2,%3};\n"
        : "+f"(c[0]), "+f"(c[1]), "+f"(c[2]), "+f"(c[3])
        : "r"(a[0]), "r"(a[1]), "r"(a[2]), "r"(a[3]), "r"(b0), "r"(b1));
}
__device__ __forceinline__ void ldsm4(uint32_t* r, uint32_t a) {
    asm volatile("ldmatrix.sync.aligned.m8n8.x4.shared.b16 {%0,%1,%2,%3}, [%4];"
                 : "=r"(r[0]), "=r"(r[1]), "=r"(r[2]), "=r"(r[3]) : "r"(a));
}
__device__ __forceinline__ void ldsm4t(uint32_t* r, uint32_t a) {
    asm volatile("ldmatrix.sync.aligned.m8n8.x4.trans.shared.b16 {%0,%1,%2,%3}, [%4];"
                 : "=r"(r[0]), "=r"(r[1]), "=r"(r[2]), "=r"(r[3]) : "r"(a));
}
__device__ __forceinline__ uint32_t pk(hf a, hf b) {
    return ((uint32_t)__half_as_ushort(b) << 16) | __half_as_ushort(a);
}
__device__ __forceinline__ void split2(float f0, float f1, uint32_t& h, uint32_t& l) {
    hf h0 = __float2half_rn(f0), h1 = __float2half_rn(f1);
    hf l0 = __float2half_rn(f0 - __half2float(h0));
    hf l1 = __float2half_rn(f1 - __half2float(h1));
    h = pk(h0, h1);
    l = pk(l0, l1);
}

// ---------------------------------------------------------------------------
// fp16 split GEMM: C[M,N] = op(A @ B^T); A[M,K], B[N,K] hi/lo half planes.
// CTA 128x128, BK=32, 8 warps (2 x 4), warp tile 64x32.
// 2-stage cp.async pipeline, __launch_bounds__(256,2) => 2 CTAs/SM.
// TERMS=3: AhBh + AhBl + AlBh; TERMS=2: AhBh + AlBh (Bl never loaded).
// smem rows: 32 halfs (64B) at 80B pitch.
// ---------------------------------------------------------------------------
template <int RELU, int SPLIT, int TERMS>
__device__ __forceinline__ void hgemm_body(
    const hf* __restrict__ Ah_, const hf* __restrict__ Al_,
    const hf* __restrict__ Bh_, const hf* __restrict__ Bl_,
    float* __restrict__ C, hf* __restrict__ Ch, hf* __restrict__ Cl,
    int M, int N, int K, int m0, int n0)
{
    constexpr int PL  = 128 * 80;                      // plane bytes
    constexpr int NBP = (TERMS == 3) ? 2 : 1;
    constexpr int STG = (2 + NBP) * PL;
    constexpr int CH  = (2 + NBP) * 128 * 4;           // 16B chunks / stage
    constexpr int CU  = CH / 256;

    extern __shared__ char smraw[];
    uint32_t sb = smem_u32(smraw);
    const int tid = threadIdx.x, lane = tid & 31, warp = tid >> 5;
    const int wr = warp >> 2, wc = warp & 3;
    const int lq = lane >> 2, lr = lane & 3;

    const hf* src[3];
    src[0] = Ah_ + (size_t)m0 * K;
    src[1] = Al_ + (size_t)m0 * K;
    src[2] = Bh_ + (size_t)n0 * K;
    const hf* srcBl = (TERMS == 3) ? Bl_ + (size_t)n0 * K : nullptr;

    auto issue = [&](int st, int k0) {
        uint32_t base = sb + (uint32_t)st * STG;
#pragma unroll
        for (int u = 0; u < CU; u++) {
            int id = tid + u * 256;
            int pl = id >> 9, rem = id & 511;
            int row = rem >> 2, c = rem & 3;
            const hf* s = (pl < 3) ? src[pl] : srcBl;
            cp_async16(base + pl * PL + row * 80 + c * 16,
                       s + (size_t)row * K + k0 + c * 8);
        }
        cp_commit();
    };

    const uint32_t a_off = (uint32_t)(wr * 64 + (lane & 15)) * 80 +
                           (uint32_t)(((lane >> 4) & 1) * 16);
    const uint32_t b_off = (uint32_t)(wc * 32 + ((lane >> 4) & 1) * 8 + (lane & 7)) * 80 +
                           (uint32_t)(((lane >> 3) & 1) * 16);

    float acc[4][4][4];
#pragma unroll
    for (int i = 0; i < 4; i++)
#pragma unroll
        for (int j = 0; j < 4; j++)
#pragma unroll
            for (int q = 0; q < 4; q++) acc[i][j][q] = 0.f;

    const int KT = K >> 5;
    issue(0, 0);
    issue(1, 32);

    for (int kt = 0; kt < KT; kt++) {
        cp_wait<1>();
        __syncthreads();

        uint32_t stg = sb + (uint32_t)(kt & 1) * STG;
#pragma unroll
        for (int ks = 0; ks < 2; ks++) {
            uint32_t ah[4][4], al[4][4];
#pragma unroll
            for (int mt = 0; mt < 4; mt++) {
                uint32_t ad = stg + a_off + mt * (16 * 80) + ks * 32;
                ldsm4(ah[mt], ad);
                ldsm4(al[mt], ad + PL);
            }
            uint32_t bh[2][4], bl[2][4];
#pragma unroll
            for (int pr = 0; pr < 2; pr++) {
                uint32_t bd = stg + 2 * PL + b_off + pr * (16 * 80) + ks * 32;
                ldsm4(bh[pr], bd);
                if (TERMS == 3) ldsm4(bl[pr], bd + PL);
            }
#pragma unroll
            for (int mt = 0; mt < 4; mt++)
#pragma unroll
                for (int pr = 0; pr < 2; pr++)
#pragma unroll
                    for (int oc = 0; oc < 2; oc++) {
                        int nt = pr * 2 + oc;
                        mma16(acc[mt][nt], ah[mt], bh[pr][2*oc], bh[pr][2*oc+1]);
                        if (TERMS == 3)
                            mma16(acc[mt][nt], ah[mt], bl[pr][2*oc], bl[pr][2*oc+1]);
                        mma16(acc[mt][nt], al[mt], bh[pr][2*oc], bh[pr][2*oc+1]);
                    }
        }
        __syncthreads();                 // all warps done reading stage kt
        if (kt + 2 < KT) issue(kt & 1, (kt + 2) * 32);
        else cp_commit();
    }

    // epilogue
#pragma unroll
    for (int mt = 0; mt < 4; mt++) {
        int r0 = m0 + wr * 64 + mt * 16 + lq;
#pragma unroll
        for (int nt = 0; nt < 4; nt++) {
            int col = n0 + wc * 32 + nt * 8 + lr * 2;
            float v0 = acc[mt][nt][0], v1 = acc[mt][nt][1];
            float v2 = acc[mt][nt][2], v3 = acc[mt][nt][3];
            if (RELU) {
                v0 = fmaxf(v0, 0.f); v1 = fmaxf(v1, 0.f);
                v2 = fmaxf(v2, 0.f); v3 = fmaxf(v3, 0.f);
            }
            if (SPLIT == 0) {
                *(float2*)(C + (size_t)r0 * N + col) = make_float2(v0, v1);
                *(float2*)(C + (size_t)(r0 + 8) * N + col) = make_float2(v2, v3);
            } else {
                uint32_t h, l;
                split2(v0, v1, h, l);
                *(uint32_t*)(Ch + (size_t)r0 * N + col) = h;
                *(uint32_t*)(Cl + (size_t)r0 * N + col) = l;
                split2(v2, v3, h, l);
                *(uint32_t*)(Ch + (size_t)(r0 + 8) * N + col) = h;
                *(uint32_t*)(Cl + (size_t)(r0 + 8) * N + col) = l;
            }
        }
    }
}

template <int RELU, int SPLIT, int TERMS, int NSWAP>
__global__ __launch_bounds__(256, 2)
void hgemm_kernel(const hf* __restrict__ Ah, const hf* __restrict__ Al,
                  const hf* __restrict__ Bh, const hf* __restrict__ Bl,
                  float* __restrict__ C, hf* __restrict__ Ch, hf* __restrict__ Cl,
                  int M, int N, int K) {
    int m0 = (NSWAP ? blockIdx.x : blockIdx.y) * 128;
    int n0 = (NSWAP ? blockIdx.y : blockIdx.x) * 128;
    hgemm_body<RELU, SPLIT, TERMS>(Ah, Al, Bh, Bl, C, Ch, Cl, M, N, K, m0, n0);
}

__global__ __launch_bounds__(256, 2)
void hgemm_qkv(const hf* __restrict__ Ah, const hf* __restrict__ Al,
               const hf* __restrict__ B0h, const hf* __restrict__ B0l,
               const hf* __restrict__ B1h, const hf* __restrict__ B1l,
               const hf* __restrict__ B2h, const hf* __restrict__ B2l,
               hf* __restrict__ C0h, hf* __restrict__ C0l,
               hf* __restrict__ C1h, hf* __restrict__ C1l,
               hf* __restrict__ C2h, hf* __restrict__ C2l,
               int M, int N, int K) {
    const hf* Bh = (blockIdx.z == 0) ? B0h : (blockIdx.z == 1) ? B1h : B2h;
    const hf* Bl = (blockIdx.z == 0) ? B0l : (blockIdx.z == 1) ? B1l : B2l;
    hf* Ch = (blockIdx.z == 0) ? C0h : (blockIdx.z == 1) ? C1h : C2h;
    hf* Cl = (blockIdx.z == 0) ? C0l : (blockIdx.z == 1) ? C1l : C2l;
    hgemm_body<0, 1, 3>(Ah, Al, Bh, Bl, nullptr, Ch, Cl, M, N, K,
                        blockIdx.y * 128, blockIdx.x * 128);
}

#define GS3 (2 * (4 * 128 * 80))   // 81920: 3-term 2-stage
#define GS2 (2 * (3 * 128 * 80))   // 61440: 2-term 2-stage

// ---------------------------------------------------------------------------
// ALL weight transposes + fp16 hi/lo splits for all layers in ONE launch.
// ---------------------------------------------------------------------------
__global__ __launch_bounds__(256)
void wconv_all(const float* __restrict__ ffw, const float* __restrict__ qw,
               const float* __restrict__ kw, const float* __restrict__ vw,
               const float* __restrict__ ow,
               hf* __restrict__ ffth, hf* __restrict__ fftl,
               hf* __restrict__ qth,  hf* __restrict__ qtl,
               hf* __restrict__ kth,  hf* __restrict__ ktl,
               hf* __restrict__ vth,  hf* __restrict__ vtl,
               hf* __restrict__ oth,  hf* __restrict__ otl) {
    __shared__ float t[32][33];
    int layer = blockIdx.y;
    int b = blockIdx.x;

    const float* W; hf* Th; hf* Tl; int R, Cc, tt;
    if (b < 4096)      { W = ffw + (size_t)layer * EDIM * FDIM;
                         Th = ffth + (size_t)layer * FDIM * EDIM;
                         Tl = fftl + (size_t)layer * FDIM * EDIM;
                         R = EDIM; Cc = FDIM; tt = b; }
    else if (b < 8192) { W = qw + (size_t)layer * FDIM * HDW;
                         Th = qth + (size_t)layer * HDW * FDIM;
                         Tl = qtl + (size_t)layer * HDW * FDIM;
                         R = FDIM; Cc = HDW; tt = b - 4096; }
    else if (b < 12288){ W = kw + (size_t)layer * FDIM * HDW;
                         Th = kth + (size_t)layer * HDW * FDIM;
                         Tl = ktl + (size_t)layer * HDW * FDIM;
                         R = FDIM; Cc = HDW; tt = b - 8192; }
    else if (b < 16384){ W = vw + (size_t)layer * FDIM * HDW;
                         Th = vth + (size_t)layer * HDW * FDIM;
                         Tl = vtl + (size_t)layer * HDW * FDIM;
                         R = FDIM; Cc = HDW; tt = b - 12288; }
    else               { W = ow + (size_t)layer * HDW * EDIM;
                         Th = oth + (size_t)layer * EDIM * HDW;
                         Tl = otl + (size_t)layer * EDIM * HDW;
                         R = HDW; Cc = EDIM; tt = b - 16384; }

    int ntx = Cc / 32;
    int c0 = (tt % ntx) * 32, r0 = (tt / ntx) * 32;
    int tx = threadIdx.x & 31, ty = threadIdx.x >> 5;
#pragma unroll
    for (int i = 0; i < 32; i += 8)
        t[ty + i][tx] = W[(size_t)(r0 + ty + i) * Cc + c0 + tx];
    __syncthreads();
#pragma unroll
    for (int i = 0; i < 32; i += 8) {
        float v = t[tx][ty + i];
        hf h = __float2half_rn(v);
        hf l = __float2half_rn(v - __half2float(h));
        size_t o = (size_t)(c0 + ty + i) * R + r0 + tx;
        Th[o] = h;
        Tl[o] = l;
    }
}

__global__ __launch_bounds__(256)
void conv_split(const float* __restrict__ X, hf* __restrict__ Xh,
                hf* __restrict__ Xl, int n4) {
    int i = blockIdx.x * 256 + threadIdx.x;
    if (i >= n4) return;
    float4 v = ((const float4*)X)[i];
    uint32_t h0, l0, h1, l1;
    split2(v.x, v.y, h0, l0);
    split2(v.z, v.w, h1, l1);
    ((uint2*)Xh)[i] = make_uint2(h0, h1);
    ((uint2*)Xl)[i] = make_uint2(l0, l1);
}

__global__ void embed_kernel(const int* __restrict__ x,
                             const float* __restrict__ emb,
                             hf* __restrict__ hh, hf* __restrict__ hl) {
    int s = blockIdx.x;
    int tok = x[s];
    const float4* src = (const float4*)(emb + (size_t)tok * EDIM);
    uint2* dh = (uint2*)(hh + (size_t)s * EDIM);
    uint2* dl = (uint2*)(hl + (size_t)s * EDIM);
    for (int i = threadIdx.x; i < EDIM / 4; i += blockDim.x) {
        float4 v = src[i];
        uint32_t h0, l0, h1, l1;
        split2(v.x, v.y, h0, l0);
        split2(v.z, v.w, h1, l1);
        dh[i] = make_uint2(h0, h1);
        dl[i] = make_uint2(l0, l1);
    }
}

// ---------------------------------------------------------------------------
// Flash attention with fp16 mma, 3-term splits for QK and PV.
// ---------------------------------------------------------------------------
#define KP    272
#define APL   (64 * KP)
#define ASTG4 (4 * APL)
#define ATT_SMEM (3 * ASTG4)

__global__ __launch_bounds__(256)
void attn_mma(const hf* __restrict__ Qh, const hf* __restrict__ Ql,
              const hf* __restrict__ Kh, const hf* __restrict__ Kl,
              const hf* __restrict__ Vh, const hf* __restrict__ Vl,
              hf* __restrict__ Oh, hf* __restrict__ Ol) {
    extern __shared__ char smraw[];
    uint32_t sb = smem_u32(smraw);
    const int tid = threadIdx.x, lane = tid & 31, warp = tid >> 5;
    const int lq = lane >> 2, lr = lane & 3;
    const int qb = blockIdx.x, head = blockIdx.y;

    {
        const hf* qsrc[2] = { Qh, Ql };
#pragma unroll
        for (int pl = 0; pl < 2; pl++)
#pragma unroll
            for (int u = 0; u < 8; u++) {
                int id = tid + u * 256;
                int row = id >> 4, c = id & 15;
                cp_async16(sb + pl * (2 * APL) + row * KP + c * 16,
                           qsrc[pl] + (size_t)(qb * 128 + row) * HDW + head * HD + c * 8);
            }
        cp_commit();
        cp_wait<0>();
        __syncthreads();
    }
    uint32_t qfh[8][4], qfl[8][4];
    {
        uint32_t q_off = (uint32_t)(warp * 16 + (lane & 15)) * KP +
                         (uint32_t)(((lane >> 4) & 1) * 16);
#pragma unroll
        for (int kc = 0; kc < 8; kc++) {
            ldsm4(qfh[kc], sb + q_off + kc * 32);
            ldsm4(qfl[kc], sb + 2 * APL + q_off + kc * 32);
        }
    }
    __syncthreads();

    const hf* kvsrc[4] = { Kh, Kl, Vh, Vl };
    auto loadKV = [&](int t, int st) {
        uint32_t base = sb + (uint32_t)st * ASTG4;
#pragma unroll
        for (int pl = 0; pl < 4; pl++)
#pragma unroll
            for (int u = 0; u < 4; u++) {
                int id = tid + u * 256;
                int row = id >> 4, c = id & 15;
                cp_async16(base + pl * APL + row * KP + c * 16,
                           kvsrc[pl] + (size_t)(t * 64 + row) * HDW + head * HD + c * 8);
            }
        cp_commit();
    };

    float o_acc[16][4];
#pragma unroll
    for (int i = 0; i < 16; i++)
#pragma unroll
        for (int j = 0; j < 4; j++) o_acc[i][j] = 0.f;
    float mrun[2] = { -1e30f, -1e30f };
    float lrun[2] = { 0.f, 0.f };

    const int NT = 2 * qb + 2;
    loadKV(0, 0);
    if (NT > 1) loadKV(1, 1);

    const uint32_t k_off = (uint32_t)(((lane >> 4) & 1) * 8 + (lane & 7)) * KP +
                           (uint32_t)(((lane >> 3) & 1) * 16);
    const uint32_t v_off = (uint32_t)(((lane >> 3) & 1) * 8 + (lane & 7)) * KP +
                           (uint32_t)(((lane >> 4) & 1) * 16);

    for (int t = 0; t < NT; t++) {
        if (t + 1 < NT) cp_wait<1>(); else cp_wait<0>();
        __syncthreads();
        if (t + 2 < NT) loadKV(t + 2, (t + 2) % 3);
        else cp_commit();

        uint32_t stg = sb + (uint32_t)(t % 3) * ASTG4;

        float s_acc[8][4];
#pragma unroll
        for (int i = 0; i < 8; i++)
#pragma unroll
            for (int j = 0; j < 4; j++) s_acc[i][j] = 0.f;

#pragma unroll
        for (int kc = 0; kc < 8; kc++) {
            uint32_t kbh[4][4], kbl[4][4];
#pragma unroll
            for (int pr = 0; pr < 4; pr++) {
                uint32_t ad = stg + k_off + pr * (16 * KP) + kc * 32;
                ldsm4(kbh[pr], ad);
                ldsm4(kbl[pr], ad + APL);
            }
#pragma unroll
            for (int pr = 0; pr < 4; pr++)
#pragma unroll
                for (int oc = 0; oc < 2; oc++) {
                    int nt = pr * 2 + oc;
                    mma16(s_acc[nt], qfh[kc], kbh[pr][2*oc], kbh[pr][2*oc+1]);
                    mma16(s_acc[nt], qfh[kc], kbl[pr][2*oc], kbl[pr][2*oc+1]);
                    mma16(s_acc[nt], qfl[kc], kbh[pr][2*oc], kbh[pr][2*oc+1]);
                }
        }

        if (t >= 2 * qb) {
            int rbase = qb * 128 + warp * 16 + lq;
#pragma unroll
            for (int nt = 0; nt < 8; nt++)
#pragma unroll
                for (int rr = 0; rr < 4; rr++) {
                    int col = t * 64 + nt * 8 + 2 * lr + (rr & 1);
                    int row = rbase + (rr >> 1) * 8;
                    if (col > row) s_acc[nt][rr] = -1e30f;
                }
        }

#pragma unroll
        for (int h = 0; h < 2; h++) {
            float mloc = -1e30f;
#pragma unroll
            for (int nt = 0; nt < 8; nt++) {
                mloc = fmaxf(mloc, s_acc[nt][2*h]);
                mloc = fmaxf(mloc, s_acc[nt][2*h+1]);
            }
            mloc = fmaxf(mloc, __shfl_xor_sync(0xffffffffu, mloc, 1));
            mloc = fmaxf(mloc, __shfl_xor_sync(0xffffffffu, mloc, 2));
            float mnew = fmaxf(mrun[h], mloc);
            float corr = __expf(mrun[h] - mnew);
            mrun[h] = mnew;
            float ps = 0.f;
#pragma unroll
            for (int nt = 0; nt < 8; nt++) {
                float p0 = __expf(s_acc[nt][2*h]   - mnew);
                float p1 = __expf(s_acc[nt][2*h+1] - mnew);
                s_acc[nt][2*h] = p0;
                s_acc[nt][2*h+1] = p1;
                ps += p0 + p1;
            }
            ps += __shfl_xor_sync(0xffffffffu, ps, 1);
            ps += __shfl_xor_sync(0xffffffffu, ps, 2);
            lrun[h] = lrun[h] * corr + ps;
#pragma unroll
            for (int nt = 0; nt < 16; nt++) {
                o_acc[nt][2*h]   *= corr;
                o_acc[nt][2*h+1] *= corr;
            }
        }

#pragma unroll
        for (int kc2 = 0; kc2 < 4; kc2++) {
            uint32_t ph[4], pl[4];
            split2(s_acc[2*kc2][0],   s_acc[2*kc2][1],   ph[0], pl[0]);
            split2(s_acc[2*kc2][2],   s_acc[2*kc2][3],   ph[1], pl[1]);
            split2(s_acc[2*kc2+1][0], s_acc[2*kc2+1][1], ph[2], pl[2]);
            split2(s_acc[2*kc2+1][2], s_acc[2*kc2+1][3], ph[3], pl[3]);
#pragma unroll
            for (int dp = 0; dp < 8; dp++) {
                uint32_t vbh[4], vbl[4];
                uint32_t ad = stg + 2 * APL + v_off + kc2 * (16 * KP) + dp * 32;
                ldsm4t(vbh, ad);
                ldsm4t(vbl, ad + APL);
#pragma unroll
                for (int oc = 0; oc < 2; oc++) {
                    int nt = dp * 2 + oc;
                    mma16(o_acc[nt], ph, vbh[2*oc], vbh[2*oc+1]);
                    mma16(o_acc[nt], ph, vbl[2*oc], vbl[2*oc+1]);
                    mma16(o_acc[nt], pl, vbh[2*oc], vbh[2*oc+1]);
                }
            }
        }
    }

    float inv0 = 1.f / lrun[0], inv1 = 1.f / lrun[1];
    int r0 = qb * 128 + warp * 16 + lq;
#pragma unroll
    for (int nt = 0; nt < 16; nt++) {
        int col = head * HD + nt * 8 + 2 * lr;
        uint32_t h, l;
        split2(o_acc[nt][0] * inv0, o_acc[nt][1] * inv0, h, l);
        *(uint32_t*)(Oh + (size_t)r0 * HDW + col) = h;
        *(uint32_t*)(Ol + (size_t)r0 * HDW + col) = l;
        split2(o_acc[nt][2] * inv1, o_acc[nt][3] * inv1, h, l);
        *(uint32_t*)(Oh + (size_t)(r0 + 8) * HDW + col) = h;
        *(uint32_t*)(Ol + (size_t)(r0 + 8) * HDW + col) = l;
    }
}

// ---------------------------------------------------------------------------
extern "C" void kernel_launch(void* const* d_in, const int* in_sizes, int n_in,
                              void* d_out, int out_size) {
    const int*   x   = (const int*)d_in[0];
    const float* emb = (const float*)d_in[1];
    const float* ffw = (const float*)d_in[2];
    const float* qw  = (const float*)d_in[3];
    const float* kw  = (const float*)d_in[4];
    const float* vw  = (const float*)d_in[5];
    const float* ow  = (const float*)d_in[6];
    float* out = (float*)d_out;

    hf *hh, *hl, *hfh, *hfl, *qh, *ql, *kh, *kl, *vh, *vl, *oh, *ol;
    hf *ffth, *fftl, *qth, *qtl, *kth, *ktl, *vth, *vtl, *oth, *otl, *eth, *etl;
    cudaGetSymbolAddress((void**)&hh,  g_hh);  cudaGetSymbolAddress((void**)&hl,  g_hl);
    cudaGetSymbolAddress((void**)&hfh, g_hfh); cudaGetSymbolAddress((void**)&hfl, g_hfl);
    cudaGetSymbolAddress((void**)&qh,  g_qh);  cudaGetSymbolAddress((void**)&ql,  g_ql);
    cudaGetSymbolAddress((void**)&kh,  g_kh);  cudaGetSymbolAddress((void**)&kl,  g_kl);
    cudaGetSymbolAddress((void**)&vh,  g_vh);  cudaGetSymbolAddress((void**)&vl,  g_vl);
    cudaGetSymbolAddress((void**)&oh,  g_oh);  cudaGetSymbolAddress((void**)&ol,  g_ol);
    cudaGetSymbolAddress((void**)&ffth, g_ffth); cudaGetSymbolAddress((void**)&fftl, g_fftl);
    cudaGetSymbolAddress((void**)&qth,  g_qth);  cudaGetSymbolAddress((void**)&qtl,  g_qtl);
    cudaGetSymbolAddress((void**)&kth,  g_kth);  cudaGetSymbolAddress((void**)&ktl,  g_ktl);
    cudaGetSymbolAddress((void**)&vth,  g_vth);  cudaGetSymbolAddress((void**)&vtl,  g_vtl);
    cudaGetSymbolAddress((void**)&oth,  g_oth);  cudaGetSymbolAddress((void**)&otl,  g_otl);
    cudaGetSymbolAddress((void**)&eth,  g_eth);  cudaGetSymbolAddress((void**)&etl,  g_etl);

    cudaFuncSetAttribute(attn_mma,
                         cudaFuncAttributeMaxDynamicSharedMemorySize, ATT_SMEM);
    cudaFuncSetAttribute(hgemm_kernel<1, 1, 3, 0>,
                         cudaFuncAttributeMaxDynamicSharedMemorySize, GS3);
    cudaFuncSetAttribute(hgemm_kernel<0, 1, 3, 0>,
                         cudaFuncAttributeMaxDynamicSharedMemorySize, GS3);
    cudaFuncSetAttribute(hgemm_kernel<0, 0, 2, 1>,
                         cudaFuncAttributeMaxDynamicSharedMemorySize, GS2);
    cudaFuncSetAttribute(hgemm_qkv,
                         cudaFuncAttributeMaxDynamicSharedMemorySize, GS3);

    embed_kernel<<<SQ, 256>>>(x, emb, hh, hl);
    conv_split<<<(VOC * EDIM / 4 + 255) / 256, 256>>>(emb, eth, etl, VOC * EDIM / 4);
    wconv_all<<<dim3(17408, NL), 256>>>(ffw, qw, kw, vw, ow,
                                        ffth, fftl, qth, qtl, kth, ktl,
                                        vth, vtl, oth, otl);

    for (int i = 0; i < NL; i++) {
        hf* ffthi = ffth + (size_t)i * FDIM * EDIM;
        hf* fftli = fftl + (size_t)i * FDIM * EDIM;
        hf* qthi  = qth  + (size_t)i * HDW * FDIM;
        hf* qtli  = qtl  + (size_t)i * HDW * FDIM;
        hf* kthi  = kth  + (size_t)i * HDW * FDIM;
        hf* ktli  = ktl  + (size_t)i * HDW * FDIM;
        hf* vthi  = vth  + (size_t)i * HDW * FDIM;
        hf* vtli  = vtl  + (size_t)i * HDW * FDIM;
        hf* othi  = oth  + (size_t)i * EDIM * HDW;
        hf* otli  = otl  + (size_t)i * EDIM * HDW;

        // hf = relu(h @ ff_w): [2048,1024] @ [1024,4096]  (512 CTAs)
        hgemm_kernel<1, 1, 3, 0><<<dim3(FDIM / 128, SQ / 128), 256, GS3>>>(
            hh, hl, ffthi, fftli, nullptr, hfh, hfl, SQ, FDIM, EDIM);

        // q,k,v = hf @ w: [2048,4096] @ [4096,1024]  (384 CTAs)
        hgemm_qkv<<<dim3(HDW / 128, SQ / 128, 3), 256, GS3>>>(
            hfh, hfl, qthi, qtli, kthi, ktli, vthi, vtli,
            qh, ql, kh, kl, vh, vl, SQ, HDW, FDIM);

        // attention
        attn_mma<<<dim3(SQ / 128, NH), 256, ATT_SMEM>>>(
            qh, ql, kh, kl, vh, vl, oh, ol);

        // h = o @ o_w: [2048,1024] @ [1024,1024]  (128 CTAs)
        hgemm_kernel<0, 1, 3, 0><<<dim3(EDIM / 128, SQ / 128), 256, GS3>>>(
            oh, ol, othi, otli, nullptr, hh, hl, SQ, EDIM, HDW);
    }

    // logits = h @ emb^T: 2-term, grid swapped (m fastest) for B-tile L2 reuse
    hgemm_kernel<0, 0, 2, 1><<<dim3(SQ / 128, VOC / 128), 256, GS2>>>(
        hh, hl, eth, etl, out, nullptr, nullptr, SQ, VOC, EDIM);
}

// round 13
// speedup vs baseline: 1.3702x; 1.1004x over previous
#include <cuda_runtime.h>
#include <cuda_fp16.h>
#include <cstdint>

#define SQ   2048
#define EDIM 1024
#define FDIM 4096
#define NH   8
#define HD   128
#define NL   4
#define VOC  32000
#define HDW  (NH * HD)     // 1024

typedef __half hf;

// ---------------------------------------------------------------------------
// static scratch: fp16 hi/lo planes
// ---------------------------------------------------------------------------
__device__ hf g_hh [SQ * EDIM];
__device__ hf g_hl [SQ * EDIM];
__device__ hf g_hfh[SQ * FDIM];
__device__ hf g_hfl[SQ * FDIM];
__device__ hf g_qh [SQ * HDW];
__device__ hf g_ql [SQ * HDW];
__device__ hf g_kh [SQ * HDW];
__device__ hf g_kl [SQ * HDW];
__device__ hf g_vh [SQ * HDW];
__device__ hf g_vl [SQ * HDW];
__device__ hf g_oh [SQ * HDW];
__device__ hf g_ol [SQ * HDW];
__device__ hf g_ffth[NL * FDIM * EDIM];
__device__ hf g_fftl[NL * FDIM * EDIM];
__device__ hf g_qth [NL * HDW * FDIM];
__device__ hf g_qtl [NL * HDW * FDIM];
__device__ hf g_kth [NL * HDW * FDIM];
__device__ hf g_ktl [NL * HDW * FDIM];
__device__ hf g_vth [NL * HDW * FDIM];
__device__ hf g_vtl [NL * HDW * FDIM];
__device__ hf g_oth [NL * EDIM * HDW];
__device__ hf g_otl [NL * EDIM * HDW];
__device__ hf g_eth [VOC * EDIM];
// attention split-KV partials
__device__ float g_opart[2 * SQ * HDW];
__device__ float g_gm  [2 * NH * SQ];
__device__ float g_gl  [2 * NH * SQ];

// ---------------------------------------------------------------------------
// helpers
// ---------------------------------------------------------------------------
__device__ __forceinline__ uint32_t smem_u32(const void* p) {
    return (uint32_t)__cvta_generic_to_shared(p);
}
__device__ __forceinline__ void cp_async16(uint32_t dst, const void* src) {
    asm volatile("cp.async.cg.shared.global [%0], [%1], 16;\n" :: "r"(dst), "l"(src));
}
__device__ __forceinline__ void cp_commit() {
    asm volatile("cp.async.commit_group;\n");
}
template <int N>
__device__ __forceinline__ void cp_wait() {
    asm volatile("cp.async.wait_group %0;\n" :: "n"(N));
}
__device__ __forceinline__ void mma16(float* c, const uint32_t* a, uint32_t b0, uint32_t b1) {
    asm volatile(
        "mma.sync.aligned.m16n8k16.row.col.f32.f16.f16.f32 "
        "{%0,%1,%2,%3}, {%4,%5,%6,%7}, {%8,%9}, {%0,%1,%2,%3};\n"
        : "+f"(c[0]), "+f"(c[1]), "+f"(c[2]), "+f"(c[3])
        : "r"(a[0]), "r"(a[1]), "r"(a[2]), "r"(a[3]), "r"(b0), "r"(b1));
}
__device__ __forceinline__ void ldsm4(uint32_t* r, uint32_t a) {
    asm volatile("ldmatrix.sync.aligned.m8n8.x4.shared.b16 {%0,%1,%2,%3}, [%4];"
                 : "=r"(r[0]), "=r"(r[1]), "=r"(r[2]), "=r"(r[3]) : "r"(a));
}
__device__ __forceinline__ void ldsm4t(uint32_t* r, uint32_t a) {
    asm volatile("ldmatrix.sync.aligned.m8n8.x4.trans.shared.b16 {%0,%1,%2,%3}, [%4];"
                 : "=r"(r[0]), "=r"(r[1]), "=r"(r[2]), "=r"(r[3]) : "r"(a));
}
__device__ __forceinline__ uint32_t pk(hf a, hf b) {
    return ((uint32_t)__half_as_ushort(b) << 16) | __half_as_ushort(a);
}
__device__ __forceinline__ void split2(float f0, float f1, uint32_t& h, uint32_t& l) {
    hf h0 = __float2half_rn(f0), h1 = __float2half_rn(f1);
    hf l0 = __float2half_rn(f0 - __half2float(h0));
    hf l1 = __float2half_rn(f1 - __half2float(h1));
    h = pk(h0, h1);
    l = pk(l0, l1);
}

// ---------------------------------------------------------------------------
// fp16 split GEMM: C[M,N] = op(A @ B^T); A[M,K], B[N,K] hi/lo half planes.
// CTA 128x128, BK=32, 8 warps (2x4), warp tile 64x32, 2-stage, 2 CTAs/SM.
// TERMS=3: AhBh+AhBl+AlBh;  TERMS=2: AhBh+AlBh;  TERMS=1: AhBh only.
// ---------------------------------------------------------------------------
template <int RELU, int SPLIT, int TERMS>
__device__ __forceinline__ void hgemm_body(
    const hf* __restrict__ Ah_, const hf* __restrict__ Al_,
    const hf* __restrict__ Bh_, const hf* __restrict__ Bl_,
    float* __restrict__ C, hf* __restrict__ Ch, hf* __restrict__ Cl,
    int M, int N, int K, int m0, int n0)
{
    constexpr int PL  = 128 * 80;                      // plane bytes
    constexpr int NAP = (TERMS == 1) ? 1 : 2;
    constexpr int NBP = (TERMS == 3) ? 2 : 1;
    constexpr int NP  = NAP + NBP;
    constexpr int STG = NP * PL;
    constexpr int CU  = NP * 2;                        // 16B chunks/thread/stage

    extern __shared__ char smraw[];
    uint32_t sb = smem_u32(smraw);
    const int tid = threadIdx.x, lane = tid & 31, warp = tid >> 5;
    const int wr = warp >> 2, wc = warp & 3;
    const int lq = lane >> 2, lr = lane & 3;

    const hf* src[4];
    {
        int n = 0;
        src[n++] = Ah_ + (size_t)m0 * K;
        if (NAP == 2) src[n++] = Al_ + (size_t)m0 * K;
        src[n++] = Bh_ + (size_t)n0 * K;
        if (NBP == 2) src[n++] = Bl_ + (size_t)n0 * K;
    }

    auto issue = [&](int st, int k0) {
        uint32_t base = sb + (uint32_t)st * STG;
#pragma unroll
        for (int u = 0; u < CU; u++) {
            int id = tid + u * 256;
            int pl = id >> 9, rem = id & 511;
            int row = rem >> 2, c = rem & 3;
            cp_async16(base + pl * PL + row * 80 + c * 16,
                       src[pl] + (size_t)row * K + k0 + c * 8);
        }
        cp_commit();
    };

    const uint32_t a_off = (uint32_t)(wr * 64 + (lane & 15)) * 80 +
                           (uint32_t)(((lane >> 4) & 1) * 16);
    const uint32_t b_off = (uint32_t)(wc * 32 + ((lane >> 4) & 1) * 8 + (lane & 7)) * 80 +
                           (uint32_t)(((lane >> 3) & 1) * 16);

    float acc[4][4][4];
#pragma unroll
    for (int i = 0; i < 4; i++)
#pragma unroll
        for (int j = 0; j < 4; j++)
#pragma unroll
            for (int q = 0; q < 4; q++) acc[i][j][q] = 0.f;

    const int KT = K >> 5;
    issue(0, 0);
    issue(1, 32);

    for (int kt = 0; kt < KT; kt++) {
        cp_wait<1>();
        __syncthreads();

        uint32_t stg = sb + (uint32_t)(kt & 1) * STG;
#pragma unroll
        for (int ks = 0; ks < 2; ks++) {
            uint32_t ah[4][4], al[4][4];
#pragma unroll
            for (int mt = 0; mt < 4; mt++) {
                uint32_t ad = stg + a_off + mt * (16 * 80) + ks * 32;
                ldsm4(ah[mt], ad);
                if (TERMS >= 2) ldsm4(al[mt], ad + PL);
            }
            uint32_t bh[2][4], bl[2][4];
#pragma unroll
            for (int pr = 0; pr < 2; pr++) {
                uint32_t bd = stg + NAP * PL + b_off + pr * (16 * 80) + ks * 32;
                ldsm4(bh[pr], bd);
                if (TERMS == 3) ldsm4(bl[pr], bd + PL);
            }
#pragma unroll
            for (int mt = 0; mt < 4; mt++)
#pragma unroll
                for (int pr = 0; pr < 2; pr++)
#pragma unroll
                    for (int oc = 0; oc < 2; oc++) {
                        int nt = pr * 2 + oc;
                        mma16(acc[mt][nt], ah[mt], bh[pr][2*oc], bh[pr][2*oc+1]);
                        if (TERMS == 3)
                            mma16(acc[mt][nt], ah[mt], bl[pr][2*oc], bl[pr][2*oc+1]);
                        if (TERMS >= 2)
                            mma16(acc[mt][nt], al[mt], bh[pr][2*oc], bh[pr][2*oc+1]);
                    }
        }
        __syncthreads();
        if (kt + 2 < KT) issue(kt & 1, (kt + 2) * 32);
        else cp_commit();
    }

    // epilogue
#pragma unroll
    for (int mt = 0; mt < 4; mt++) {
        int r0 = m0 + wr * 64 + mt * 16 + lq;
#pragma unroll
        for (int nt = 0; nt < 4; nt++) {
            int col = n0 + wc * 32 + nt * 8 + lr * 2;
            float v0 = acc[mt][nt][0], v1 = acc[mt][nt][1];
            float v2 = acc[mt][nt][2], v3 = acc[mt][nt][3];
            if (RELU) {
                v0 = fmaxf(v0, 0.f); v1 = fmaxf(v1, 0.f);
                v2 = fmaxf(v2, 0.f); v3 = fmaxf(v3, 0.f);
            }
            if (SPLIT == 0) {
                *(float2*)(C + (size_t)r0 * N + col) = make_float2(v0, v1);
                *(float2*)(C + (size_t)(r0 + 8) * N + col) = make_float2(v2, v3);
            } else {
                uint32_t h, l;
                split2(v0, v1, h, l);
                *(uint32_t*)(Ch + (size_t)r0 * N + col) = h;
                *(uint32_t*)(Cl + (size_t)r0 * N + col) = l;
                split2(v2, v3, h, l);
                *(uint32_t*)(Ch + (size_t)(r0 + 8) * N + col) = h;
                *(uint32_t*)(Cl + (size_t)(r0 + 8) * N + col) = l;
            }
        }
    }
}

template <int RELU, int SPLIT, int TERMS, int NSWAP>
__global__ __launch_bounds__(256, 2)
void hgemm_kernel(const hf* __restrict__ Ah, const hf* __restrict__ Al,
                  const hf* __restrict__ Bh, const hf* __restrict__ Bl,
                  float* __restrict__ C, hf* __restrict__ Ch, hf* __restrict__ Cl,
                  int M, int N, int K) {
    int m0 = (NSWAP ? blockIdx.x : blockIdx.y) * 128;
    int n0 = (NSWAP ? blockIdx.y : blockIdx.x) * 128;
    hgemm_body<RELU, SPLIT, TERMS>(Ah, Al, Bh, Bl, C, Ch, Cl, M, N, K, m0, n0);
}

__global__ __launch_bounds__(256, 2)
void hgemm_qkv(const hf* __restrict__ Ah, const hf* __restrict__ Al,
               const hf* __restrict__ B0h, const hf* __restrict__ B0l,
               const hf* __restrict__ B1h, const hf* __restrict__ B1l,
               const hf* __restrict__ B2h, const hf* __restrict__ B2l,
               hf* __restrict__ C0h, hf* __restrict__ C0l,
               hf* __restrict__ C1h, hf* __restrict__ C1l,
               hf* __restrict__ C2h, hf* __restrict__ C2l,
               int M, int N, int K) {
    const hf* Bh = (blockIdx.z == 0) ? B0h : (blockIdx.z == 1) ? B1h : B2h;
    const hf* Bl = (blockIdx.z == 0) ? B0l : (blockIdx.z == 1) ? B1l : B2l;
    hf* Ch = (blockIdx.z == 0) ? C0h : (blockIdx.z == 1) ? C1h : C2h;
    hf* Cl = (blockIdx.z == 0) ? C0l : (blockIdx.z == 1) ? C1l : C2l;
    hgemm_body<0, 1, 3>(Ah, Al, Bh, Bl, nullptr, Ch, Cl, M, N, K,
                        blockIdx.y * 128, blockIdx.x * 128);
}

#define GS3 (2 * (4 * 128 * 80))   // 81920
#define GS1 (2 * (2 * 128 * 80))   // 40960

// ---------------------------------------------------------------------------
// ALL weight transposes + fp16 hi/lo splits for all layers in ONE launch.
// ---------------------------------------------------------------------------
__global__ __launch_bounds__(256)
void wconv_all(const float* __restrict__ ffw, const float* __restrict__ qw,
               const float* __restrict__ kw, const float* __restrict__ vw,
               const float* __restrict__ ow,
               hf* __restrict__ ffth, hf* __restrict__ fftl,
               hf* __restrict__ qth,  hf* __restrict__ qtl,
               hf* __restrict__ kth,  hf* __restrict__ ktl,
               hf* __restrict__ vth,  hf* __restrict__ vtl,
               hf* __restrict__ oth,  hf* __restrict__ otl) {
    __shared__ float t[32][33];
    int layer = blockIdx.y;
    int b = blockIdx.x;

    const float* W; hf* Th; hf* Tl; int R, Cc, tt;
    if (b < 4096)      { W = ffw + (size_t)layer * EDIM * FDIM;
                         Th = ffth + (size_t)layer * FDIM * EDIM;
                         Tl = fftl + (size_t)layer * FDIM * EDIM;
                         R = EDIM; Cc = FDIM; tt = b; }
    else if (b < 8192) { W = qw + (size_t)layer * FDIM * HDW;
                         Th = qth + (size_t)layer * HDW * FDIM;
                         Tl = qtl + (size_t)layer * HDW * FDIM;
                         R = FDIM; Cc = HDW; tt = b - 4096; }
    else if (b < 12288){ W = kw + (size_t)layer * FDIM * HDW;
                         Th = kth + (size_t)layer * HDW * FDIM;
                         Tl = ktl + (size_t)layer * HDW * FDIM;
                         R = FDIM; Cc = HDW; tt = b - 8192; }
    else if (b < 16384){ W = vw + (size_t)layer * FDIM * HDW;
                         Th = vth + (size_t)layer * HDW * FDIM;
                         Tl = vtl + (size_t)layer * HDW * FDIM;
                         R = FDIM; Cc = HDW; tt = b - 12288; }
    else               { W = ow + (size_t)layer * HDW * EDIM;
                         Th = oth + (size_t)layer * EDIM * HDW;
                         Tl = otl + (size_t)layer * EDIM * HDW;
                         R = HDW; Cc = EDIM; tt = b - 16384; }

    int ntx = Cc / 32;
    int c0 = (tt % ntx) * 32, r0 = (tt / ntx) * 32;
    int tx = threadIdx.x & 31, ty = threadIdx.x >> 5;
#pragma unroll
    for (int i = 0; i < 32; i += 8)
        t[ty + i][tx] = W[(size_t)(r0 + ty + i) * Cc + c0 + tx];
    __syncthreads();
#pragma unroll
    for (int i = 0; i < 32; i += 8) {
        float v = t[tx][ty + i];
        hf h = __float2half_rn(v);
        hf l = __float2half_rn(v - __half2float(h));
        size_t o = (size_t)(c0 + ty + i) * R + r0 + tx;
        Th[o] = h;
        Tl[o] = l;
    }
}

// hi-only fp16 conversion (embedding matrix for 1-term logits)
__global__ __launch_bounds__(256)
void conv_h(const float* __restrict__ X, hf* __restrict__ Xh, int n4) {
    int i = blockIdx.x * 256 + threadIdx.x;
    if (i >= n4) return;
    float4 v = ((const float4*)X)[i];
    uint32_t h0 = pk(__float2half_rn(v.x), __float2half_rn(v.y));
    uint32_t h1 = pk(__float2half_rn(v.z), __float2half_rn(v.w));
    ((uint2*)Xh)[i] = make_uint2(h0, h1);
}

__global__ void embed_kernel(const int* __restrict__ x,
                             const float* __restrict__ emb,
                             hf* __restrict__ hh, hf* __restrict__ hl) {
    int s = blockIdx.x;
    int tok = x[s];
    const float4* src = (const float4*)(emb + (size_t)tok * EDIM);
    uint2* dh = (uint2*)(hh + (size_t)s * EDIM);
    uint2* dl = (uint2*)(hl + (size_t)s * EDIM);
    for (int i = threadIdx.x; i < EDIM / 4; i += blockDim.x) {
        float4 v = src[i];
        uint32_t h0, l0, h1, l1;
        split2(v.x, v.y, h0, l0);
        split2(v.z, v.w, h1, l1);
        dh[i] = make_uint2(h0, h1);
        dl[i] = make_uint2(l0, l1);
    }
}

// ---------------------------------------------------------------------------
// Flash attention, split-KV: CTA = (qb, head, half). Each half processes
// qb+1 of the 2qb+2 key tiles; partial (unnormalized O, m, l) to gmem;
// attn_merge recombines (numerically exact).
// ---------------------------------------------------------------------------
#define KP    272
#define APL   (64 * KP)
#define ASTG4 (4 * APL)
#define ATT_SMEM (3 * ASTG4)

__global__ __launch_bounds__(256)
void attn_mma(const hf* __restrict__ Qh, const hf* __restrict__ Ql,
              const hf* __restrict__ Kh, const hf* __restrict__ Kl,
              const hf* __restrict__ Vh, const hf* __restrict__ Vl,
              float* __restrict__ opart, float* __restrict__ gm,
              float* __restrict__ gl) {
    extern __shared__ char smraw[];
    uint32_t sb = smem_u32(smraw);
    const int tid = threadIdx.x, lane = tid & 31, warp = tid >> 5;
    const int lq = lane >> 2, lr = lane & 3;
    const int qb = (SQ / 128 - 1) - blockIdx.x;   // descending: big CTAs first
    const int head = blockIdx.y;
    const int half = blockIdx.z;

    const int T0 = (half == 0) ? 0 : qb + 1;
    const int NT = qb + 1;

    {
        const hf* qsrc[2] = { Qh, Ql };
#pragma unroll
        for (int pl = 0; pl < 2; pl++)
#pragma unroll
            for (int u = 0; u < 8; u++) {
                int id = tid + u * 256;
                int row = id >> 4, c = id & 15;
                cp_async16(sb + pl * (2 * APL) + row * KP + c * 16,
                           qsrc[pl] + (size_t)(qb * 128 + row) * HDW + head * HD + c * 8);
            }
        cp_commit();
        cp_wait<0>();
        __syncthreads();
    }
    uint32_t qfh[8][4], qfl[8][4];
    {
        uint32_t q_off = (uint32_t)(warp * 16 + (lane & 15)) * KP +
                         (uint32_t)(((lane >> 4) & 1) * 16);
#pragma unroll
        for (int kc = 0; kc < 8; kc++) {
            ldsm4(qfh[kc], sb + q_off + kc * 32);
            ldsm4(qfl[kc], sb + 2 * APL + q_off + kc * 32);
        }
    }
    __syncthreads();

    const hf* kvsrc[4] = { Kh, Kl, Vh, Vl };
    auto loadKV = [&](int t, int st) {
        uint32_t base = sb + (uint32_t)st * ASTG4;
#pragma unroll
        for (int pl = 0; pl < 4; pl++)
#pragma unroll
            for (int u = 0; u < 4; u++) {
                int id = tid + u * 256;
                int row = id >> 4, c = id & 15;
                cp_async16(base + pl * APL + row * KP + c * 16,
                           kvsrc[pl] + (size_t)(t * 64 + row) * HDW + head * HD + c * 8);
            }
        cp_commit();
    };

    float o_acc[16][4];
#pragma unroll
    for (int i = 0; i < 16; i++)
#pragma unroll
        for (int j = 0; j < 4; j++) o_acc[i][j] = 0.f;
    float mrun[2] = { -1e30f, -1e30f };
    float lrun[2] = { 0.f, 0.f };

    loadKV(T0, 0);
    if (NT > 1) loadKV(T0 + 1, 1);

    const uint32_t k_off = (uint32_t)(((lane >> 4) & 1) * 8 + (lane & 7)) * KP +
                           (uint32_t)(((lane >> 3) & 1) * 16);
    const uint32_t v_off = (uint32_t)(((lane >> 3) & 1) * 8 + (lane & 7)) * KP +
                           (uint32_t)(((lane >> 4) & 1) * 16);

    for (int tt = 0; tt < NT; tt++) {
        const int t = T0 + tt;
        if (tt + 1 < NT) cp_wait<1>(); else cp_wait<0>();
        __syncthreads();
        if (tt + 2 < NT) loadKV(T0 + tt + 2, (tt + 2) % 3);
        else cp_commit();

        uint32_t stg = sb + (uint32_t)(tt % 3) * ASTG4;

        float s_acc[8][4];
#pragma unroll
        for (int i = 0; i < 8; i++)
#pragma unroll
            for (int j = 0; j < 4; j++) s_acc[i][j] = 0.f;

#pragma unroll
        for (int kc = 0; kc < 8; kc++) {
            uint32_t kbh[4][4], kbl[4][4];
#pragma unroll
            for (int pr = 0; pr < 4; pr++) {
                uint32_t ad = stg + k_off + pr * (16 * KP) + kc * 32;
                ldsm4(kbh[pr], ad);
                ldsm4(kbl[pr], ad + APL);
            }
#pragma unroll
            for (int pr = 0; pr < 4; pr++)
#pragma unroll
                for (int oc = 0; oc < 2; oc++) {
                    int nt = pr * 2 + oc;
                    mma16(s_acc[nt], qfh[kc], kbh[pr][2*oc], kbh[pr][2*oc+1]);
                    mma16(s_acc[nt], qfh[kc], kbl[pr][2*oc], kbl[pr][2*oc+1]);
                    mma16(s_acc[nt], qfl[kc], kbh[pr][2*oc], kbh[pr][2*oc+1]);
                }
        }

        if (t >= 2 * qb) {
            int rbase = qb * 128 + warp * 16 + lq;
#pragma unroll
            for (int nt = 0; nt < 8; nt++)
#pragma unroll
                for (int rr = 0; rr < 4; rr++) {
                    int col = t * 64 + nt * 8 + 2 * lr + (rr & 1);
                    int row = rbase + (rr >> 1) * 8;
                    if (col > row) s_acc[nt][rr] = -1e30f;
                }
        }

#pragma unroll
        for (int h = 0; h < 2; h++) {
            float mloc = -1e30f;
#pragma unroll
            for (int nt = 0; nt < 8; nt++) {
                mloc = fmaxf(mloc, s_acc[nt][2*h]);
                mloc = fmaxf(mloc, s_acc[nt][2*h+1]);
            }
            mloc = fmaxf(mloc, __shfl_xor_sync(0xffffffffu, mloc, 1));
            mloc = fmaxf(mloc, __shfl_xor_sync(0xffffffffu, mloc, 2));
            float mnew = fmaxf(mrun[h], mloc);
            float live = (mnew > -1e29f) ? 1.f : 0.f;   // dead-row guard
            float corr = __expf(mrun[h] - mnew);
            mrun[h] = mnew;
            float ps = 0.f;
#pragma unroll
            for (int nt = 0; nt < 8; nt++) {
                float p0 = live * __expf(s_acc[nt][2*h]   - mnew);
                float p1 = live * __expf(s_acc[nt][2*h+1] - mnew);
                s_acc[nt][2*h] = p0;
                s_acc[nt][2*h+1] = p1;
                ps += p0 + p1;
            }
            ps += __shfl_xor_sync(0xffffffffu, ps, 1);
            ps += __shfl_xor_sync(0xffffffffu, ps, 2);
            lrun[h] = lrun[h] * corr + ps;
#pragma unroll
            for (int nt = 0; nt < 16; nt++) {
                o_acc[nt][2*h]   *= corr;
                o_acc[nt][2*h+1] *= corr;
            }
        }

#pragma unroll
        for (int kc2 = 0; kc2 < 4; kc2++) {
            uint32_t ph[4], pl[4];
            split2(s_acc[2*kc2][0],   s_acc[2*kc2][1],   ph[0], pl[0]);
            split2(s_acc[2*kc2][2],   s_acc[2*kc2][3],   ph[1], pl[1]);
            split2(s_acc[2*kc2+1][0], s_acc[2*kc2+1][1], ph[2], pl[2]);
            split2(s_acc[2*kc2+1][2], s_acc[2*kc2+1][3], ph[3], pl[3]);
#pragma unroll
            for (int dp = 0; dp < 8; dp++) {
                uint32_t vbh[4], vbl[4];
                uint32_t ad = stg + 2 * APL + v_off + kc2 * (16 * KP) + dp * 32;
                ldsm4t(vbh, ad);
                ldsm4t(vbl, ad + APL);
#pragma unroll
                for (int oc = 0; oc < 2; oc++) {
                    int nt = dp * 2 + oc;
                    mma16(o_acc[nt], ph, vbh[2*oc], vbh[2*oc+1]);
                    mma16(o_acc[nt], ph, vbl[2*oc], vbl[2*oc+1]);
                    mma16(o_acc[nt], pl, vbh[2*oc], vbh[2*oc+1]);
                }
            }
        }
    }

    // epilogue: write UNnormalized partials + (m, l)
    float* op = opart + (size_t)half * SQ * HDW;
    int r0 = qb * 128 + warp * 16 + lq;
#pragma unroll
    for (int nt = 0; nt < 16; nt++) {
        int col = head * HD + nt * 8 + 2 * lr;
        *(float2*)(op + (size_t)r0 * HDW + col) =
            make_float2(o_acc[nt][0], o_acc[nt][1]);
        *(float2*)(op + (size_t)(r0 + 8) * HDW + col) =
            make_float2(o_acc[nt][2], o_acc[nt][3]);
    }
    if (lr == 0) {
        int base = half * NH * SQ + head * SQ;
        gm[base + r0] = mrun[0];
        gl[base + r0] = lrun[0];
        gm[base + r0 + 8] = mrun[1];
        gl[base + r0 + 8] = lrun[1];
    }
}

// merge the two KV halves; write fp16 hi/lo planes of O
__global__ __launch_bounds__(256)
void attn_merge(const float* __restrict__ opart, const float* __restrict__ gm,
                const float* __restrict__ gl,
                hf* __restrict__ Oh, hf* __restrict__ Ol) {
    int row = blockIdx.x;
    int head = threadIdx.x >> 5;
    int lane = threadIdx.x & 31;

    int base = head * SQ + row;
    float m0 = gm[base],          m1 = gm[NH * SQ + base];
    float l0 = gl[base],          l1 = gl[NH * SQ + base];
    float mx = fmaxf(m0, m1);
    float e0 = __expf(m0 - mx), e1 = __expf(m1 - mx);
    float inv = 1.f / (l0 * e0 + l1 * e1);

    size_t off = (size_t)row * HDW + head * HD + lane * 4;
    float4 a = *(const float4*)(opart + off);
    float4 b = *(const float4*)(opart + (size_t)SQ * HDW + off);
    float o0 = (e0 * a.x + e1 * b.x) * inv;
    float o1 = (e0 * a.y + e1 * b.y) * inv;
    float o2 = (e0 * a.z + e1 * b.z) * inv;
    float o3 = (e0 * a.w + e1 * b.w) * inv;

    uint32_t h, l;
    split2(o0, o1, h, l);
    *(uint32_t*)(Oh + off) = h;
    *(uint32_t*)(Ol + off) = l;
    split2(o2, o3, h, l);
    *(uint32_t*)(Oh + off + 2) = h;
    *(uint32_t*)(Ol + off + 2) = l;
}

// ---------------------------------------------------------------------------
extern "C" void kernel_launch(void* const* d_in, const int* in_sizes, int n_in,
                              void* d_out, int out_size) {
    const int*   x   = (const int*)d_in[0];
    const float* emb = (const float*)d_in[1];
    const float* ffw = (const float*)d_in[2];
    const float* qw  = (const float*)d_in[3];
    const float* kw  = (const float*)d_in[4];
    const float* vw  = (const float*)d_in[5];
    const float* ow  = (const float*)d_in[6];
    float* out = (float*)d_out;

    hf *hh, *hl, *hfh, *hfl, *qh, *ql, *kh, *kl, *vh, *vl, *oh, *ol;
    hf *ffth, *fftl, *qth, *qtl, *kth, *ktl, *vth, *vtl, *oth, *otl, *eth;
    float *opart, *gmM, *gmL;
    cudaGetSymbolAddress((void**)&hh,  g_hh);  cudaGetSymbolAddress((void**)&hl,  g_hl);
    cudaGetSymbolAddress((void**)&hfh, g_hfh); cudaGetSymbolAddress((void**)&hfl, g_hfl);
    cudaGetSymbolAddress((void**)&qh,  g_qh);  cudaGetSymbolAddress((void**)&ql,  g_ql);
    cudaGetSymbolAddress((void**)&kh,  g_kh);  cudaGetSymbolAddress((void**)&kl,  g_kl);
    cudaGetSymbolAddress((void**)&vh,  g_vh);  cudaGetSymbolAddress((void**)&vl,  g_vl);
    cudaGetSymbolAddress((void**)&oh,  g_oh);  cudaGetSymbolAddress((void**)&ol,  g_ol);
    cudaGetSymbolAddress((void**)&ffth, g_ffth); cudaGetSymbolAddress((void**)&fftl, g_fftl);
    cudaGetSymbolAddress((void**)&qth,  g_qth);  cudaGetSymbolAddress((void**)&qtl,  g_qtl);
    cudaGetSymbolAddress((void**)&kth,  g_kth);  cudaGetSymbolAddress((void**)&ktl,  g_ktl);
    cudaGetSymbolAddress((void**)&vth,  g_vth);  cudaGetSymbolAddress((void**)&vtl,  g_vtl);
    cudaGetSymbolAddress((void**)&oth,  g_oth);  cudaGetSymbolAddress((void**)&otl,  g_otl);
    cudaGetSymbolAddress((void**)&eth,  g_eth);
    cudaGetSymbolAddress((void**)&opart, g_opart);
    cudaGetSymbolAddress((void**)&gmM,   g_gm);
    cudaGetSymbolAddress((void**)&gmL,   g_gl);

    cudaFuncSetAttribute(attn_mma,
                         cudaFuncAttributeMaxDynamicSharedMemorySize, ATT_SMEM);
    cudaFuncSetAttribute(hgemm_kernel<1, 1, 3, 0>,
                         cudaFuncAttributeMaxDynamicSharedMemorySize, GS3);
    cudaFuncSetAttribute(hgemm_kernel<0, 1, 3, 0>,
                         cudaFuncAttributeMaxDynamicSharedMemorySize, GS3);
    cudaFuncSetAttribute(hgemm_kernel<0, 0, 1, 1>,
                         cudaFuncAttributeMaxDynamicSharedMemorySize, GS1);
    cudaFuncSetAttribute(hgemm_qkv,
                         cudaFuncAttributeMaxDynamicSharedMemorySize, GS3);

    embed_kernel<<<SQ, 256>>>(x, emb, hh, hl);
    conv_h<<<(VOC * EDIM / 4 + 255) / 256, 256>>>(emb, eth, VOC * EDIM / 4);
    wconv_all<<<dim3(17408, NL), 256>>>(ffw, qw, kw, vw, ow,
                                        ffth, fftl, qth, qtl, kth, ktl,
                                        vth, vtl, oth, otl);

    for (int i = 0; i < NL; i++) {
        hf* ffthi = ffth + (size_t)i * FDIM * EDIM;
        hf* fftli = fftl + (size_t)i * FDIM * EDIM;
        hf* qthi  = qth  + (size_t)i * HDW * FDIM;
        hf* qtli  = qtl  + (size_t)i * HDW * FDIM;
        hf* kthi  = kth  + (size_t)i * HDW * FDIM;
        hf* ktli  = ktl  + (size_t)i * HDW * FDIM;
        hf* vthi  = vth  + (size_t)i * HDW * FDIM;
        hf* vtli  = vtl  + (size_t)i * HDW * FDIM;
        hf* othi  = oth  + (size_t)i * EDIM * HDW;
        hf* otli  = otl  + (size_t)i * EDIM * HDW;

        // hf = relu(h @ ff_w): 3-term  (512 CTAs)
        hgemm_kernel<1, 1, 3, 0><<<dim3(FDIM / 128, SQ / 128), 256, GS3>>>(
            hh, hl, ffthi, fftli, nullptr, hfh, hfl, SQ, FDIM, EDIM);

        // q,k,v = hf @ w: 3-term  (384 CTAs)
        hgemm_qkv<<<dim3(HDW / 128, SQ / 128, 3), 256, GS3>>>(
            hfh, hfl, qthi, qtli, kthi, ktli, vthi, vtli,
            qh, ql, kh, kl, vh, vl, SQ, HDW, FDIM);

        // attention: split-KV (256 balanced CTAs) + merge
        attn_mma<<<dim3(SQ / 128, NH, 2), 256, ATT_SMEM>>>(
            qh, ql, kh, kl, vh, vl, opart, gmM, gmL);
        attn_merge<<<SQ, 256>>>(opart, gmM, gmL, oh, ol);

        // h = o @ o_w: 3-term  (128 CTAs)
        hgemm_kernel<0, 1, 3, 0><<<dim3(EDIM / 128, SQ / 128), 256, GS3>>>(
            oh, ol, othi, otli, nullptr, hh, hl, SQ, EDIM, HDW);
    }

    // logits = h @ emb^T: 1-term (pure fp16), grid swapped for B-tile L2 reuse
    hgemm_kernel<0, 0, 1, 1><<<dim3(SQ / 128, VOC / 128), 256, GS1>>>(
        hh, hl, eth, nullptr, out, nullptr, nullptr, SQ, VOC, EDIM);
}

// round 15
// speedup vs baseline: 1.4043x; 1.0249x over previous
#include <cuda_runtime.h>
#include <cuda_fp16.h>
#include <cstdint>

#define SQ   2048
#define EDIM 1024
#define FDIM 4096
#define NH   8
#define HD   128
#define NL   4
#define VOC  32000
#define HDW  (NH * HD)     // 1024

typedef __half hf;

// ---------------------------------------------------------------------------
// static scratch: fp16 hi/lo planes
// ---------------------------------------------------------------------------
__device__ hf g_hh [SQ * EDIM];
__device__ hf g_hl [SQ * EDIM];
__device__ hf g_hfh[SQ * FDIM];
__device__ hf g_hfl[SQ * FDIM];
__device__ hf g_qh [SQ * HDW];
__device__ hf g_ql [SQ * HDW];
__device__ hf g_kh [SQ * HDW];
__device__ hf g_kl [SQ * HDW];
__device__ hf g_vh [SQ * HDW];
__device__ hf g_vl [SQ * HDW];
__device__ hf g_oh [SQ * HDW];
__device__ hf g_ol [SQ * HDW];
__device__ hf g_ffth[NL * FDIM * EDIM];
__device__ hf g_fftl[NL * FDIM * EDIM];
__device__ hf g_qth [NL * HDW * FDIM];
__device__ hf g_qtl [NL * HDW * FDIM];
__device__ hf g_kth [NL * HDW * FDIM];
__device__ hf g_ktl [NL * HDW * FDIM];
__device__ hf g_vth [NL * HDW * FDIM];
__device__ hf g_vtl [NL * HDW * FDIM];
__device__ hf g_oth [NL * EDIM * HDW];
__device__ hf g_otl [NL * EDIM * HDW];
__device__ hf g_eth [VOC * EDIM];
// attention split-KV partials
__device__ float g_opart[2 * SQ * HDW];
__device__ float g_gm  [2 * NH * SQ];
__device__ float g_gl  [2 * NH * SQ];

// ---------------------------------------------------------------------------
// helpers
// ---------------------------------------------------------------------------
__device__ __forceinline__ uint32_t smem_u32(const void* p) {
    return (uint32_t)__cvta_generic_to_shared(p);
}
__device__ __forceinline__ void cp_async16(uint32_t dst, const void* src) {
    asm volatile("cp.async.cg.shared.global [%0], [%1], 16;\n" :: "r"(dst), "l"(src));
}
__device__ __forceinline__ void cp_commit() {
    asm volatile("cp.async.commit_group;\n");
}
template <int N>
__device__ __forceinline__ void cp_wait() {
    asm volatile("cp.async.wait_group %0;\n" :: "n"(N));
}
__device__ __forceinline__ void mma16(float* c, const uint32_t* a, uint32_t b0, uint32_t b1) {
    asm volatile(
        "mma.sync.aligned.m16n8k16.row.col.f32.f16.f16.f32 "
        "{%0,%1,%2,%3}, {%4,%5,%6,%7}, {%8,%9}, {%0,%1,%2,%3};\n"
        : "+f"(c[0]), "+f"(c[1]), "+f"(c[2]), "+f"(c[3])
        : "r"(a[0]), "r"(a[1]), "r"(a[2]), "r"(a[3]), "r"(b0), "r"(b1));
}
__device__ __forceinline__ void ldsm4(uint32_t* r, uint32_t a) {
    asm volatile("ldmatrix.sync.aligned.m8n8.x4.shared.b16 {%0,%1,%2,%3}, [%4];"
                 : "=r"(r[0]), "=r"(r[1]), "=r"(r[2]), "=r"(r[3]) : "r"(a));
}
__device__ __forceinline__ void ldsm4t(uint32_t* r, uint32_t a) {
    asm volatile("ldmatrix.sync.aligned.m8n8.x4.trans.shared.b16 {%0,%1,%2,%3}, [%4];"
                 : "=r"(r[0]), "=r"(r[1]), "=r"(r[2]), "=r"(r[3]) : "r"(a));
}
__device__ __forceinline__ uint32_t pk(hf a, hf b) {
    return ((uint32_t)__half_as_ushort(b) << 16) | __half_as_ushort(a);
}
__device__ __forceinline__ void split2(float f0, float f1, uint32_t& h, uint32_t& l) {
    hf h0 = __float2half_rn(f0), h1 = __float2half_rn(f1);
    hf l0 = __float2half_rn(f0 - __half2float(h0));
    hf l1 = __float2half_rn(f1 - __half2float(h1));
    h = pk(h0, h1);
    l = pk(l0, l1);
}

// ---------------------------------------------------------------------------
// fp16 split GEMM: C[M,N] = op(A @ B^T); A[M,K], B[N,K] hi/lo half planes.
// CTA BMT x 128, BK=32, 8 warps (2x4), warp tile (BMT/2)x32, 2-stage,
// 2 CTAs/SM. TERMS=3: AhBh+AhBl+AlBh; TERMS=2: +AlBh only; TERMS=1: AhBh.
// ---------------------------------------------------------------------------
template <int RELU, int SPLIT, int TERMS, int BMT>
__device__ __forceinline__ void hgemm_body(
    const hf* __restrict__ Ah_, const hf* __restrict__ Al_,
    const hf* __restrict__ Bh_, const hf* __restrict__ Bl_,
    float* __restrict__ C, hf* __restrict__ Ch, hf* __restrict__ Cl,
    int M, int N, int K, int m0, int n0)
{
    constexpr int PLA = BMT * 80;
    constexpr int PLB = 128 * 80;
    constexpr int NAP = (TERMS == 1) ? 1 : 2;
    constexpr int NBP = (TERMS == 3) ? 2 : 1;
    constexpr int STG = NAP * PLA + NBP * PLB;
    constexpr int ACH = NAP * BMT * 4;                 // A 16B chunks / stage
    constexpr int BCH = NBP * 128 * 4;
    constexpr int CU  = (ACH + BCH) / 256;
    constexpr int WM  = BMT / 2;
    constexpr int MT  = WM / 16;

    extern __shared__ char smraw[];
    uint32_t sb = smem_u32(smraw);
    const int tid = threadIdx.x, lane = tid & 31, warp = tid >> 5;
    const int wr = warp >> 2, wc = warp & 3;
    const int lq = lane >> 2, lr = lane & 3;

    const hf* srcA[2] = { Ah_ + (size_t)m0 * K,
                          (NAP == 2) ? Al_ + (size_t)m0 * K : Ah_ };
    const hf* srcB[2] = { Bh_ + (size_t)n0 * K,
                          (NBP == 2) ? Bl_ + (size_t)n0 * K : Bh_ };

    auto issue = [&](int st, int k0) {
        uint32_t base = sb + (uint32_t)st * STG;
#pragma unroll
        for (int u = 0; u < CU; u++) {
            int id = tid + u * 256;
            if (id < ACH) {
                int pl = id / (BMT * 4), rem = id % (BMT * 4);
                int row = rem >> 2, c = rem & 3;
                cp_async16(base + pl * PLA + row * 80 + c * 16,
                           srcA[pl] + (size_t)row * K + k0 + c * 8);
            } else {
                int id2 = id - ACH;
                int pl = id2 >> 9, rem = id2 & 511;
                int row = rem >> 2, c = rem & 3;
                cp_async16(base + NAP * PLA + pl * PLB + row * 80 + c * 16,
                           srcB[pl] + (size_t)row * K + k0 + c * 8);
            }
        }
        cp_commit();
    };

    const uint32_t a_off = (uint32_t)(wr * WM + (lane & 15)) * 80 +
                           (uint32_t)(((lane >> 4) & 1) * 16);
    const uint32_t b_off = (uint32_t)(wc * 32 + ((lane >> 4) & 1) * 8 + (lane & 7)) * 80 +
                           (uint32_t)(((lane >> 3) & 1) * 16);

    float acc[MT][4][4];
#pragma unroll
    for (int i = 0; i < MT; i++)
#pragma unroll
        for (int j = 0; j < 4; j++)
#pragma unroll
            for (int q = 0; q < 4; q++) acc[i][j][q] = 0.f;

    const int KT = K >> 5;
    issue(0, 0);
    issue(1, 32);

    for (int kt = 0; kt < KT; kt++) {
        if (kt + 1 < KT) cp_wait<1>(); else cp_wait<0>();
        __syncthreads();

        uint32_t stg = sb + (uint32_t)(kt & 1) * STG;
#pragma unroll
        for (int ks = 0; ks < 2; ks++) {
            uint32_t ah[MT][4], al[MT][4];
#pragma unroll
            for (int mt = 0; mt < MT; mt++) {
                uint32_t ad = stg + a_off + mt * (16 * 80) + ks * 32;
                ldsm4(ah[mt], ad);
                if (TERMS >= 2) ldsm4(al[mt], ad + PLA);
            }
            uint32_t bh[2][4], bl[2][4];
#pragma unroll
            for (int pr = 0; pr < 2; pr++) {
                uint32_t bd = stg + NAP * PLA + b_off + pr * (16 * 80) + ks * 32;
                ldsm4(bh[pr], bd);
                if (TERMS == 3) ldsm4(bl[pr], bd + PLB);
            }
#pragma unroll
            for (int mt = 0; mt < MT; mt++)
#pragma unroll
                for (int pr = 0; pr < 2; pr++)
#pragma unroll
                    for (int oc = 0; oc < 2; oc++) {
                        int nt = pr * 2 + oc;
                        mma16(acc[mt][nt], ah[mt], bh[pr][2*oc], bh[pr][2*oc+1]);
                        if (TERMS == 3)
                            mma16(acc[mt][nt], ah[mt], bl[pr][2*oc], bl[pr][2*oc+1]);
                        if (TERMS >= 2)
                            mma16(acc[mt][nt], al[mt], bh[pr][2*oc], bh[pr][2*oc+1]);
                    }
        }
        __syncthreads();
        if (kt + 2 < KT) issue(kt & 1, (kt + 2) * 32);
        else cp_commit();
    }

    // epilogue
#pragma unroll
    for (int mt = 0; mt < MT; mt++) {
        int r0 = m0 + wr * WM + mt * 16 + lq;
#pragma unroll
        for (int nt = 0; nt < 4; nt++) {
            int col = n0 + wc * 32 + nt * 8 + lr * 2;
            float v0 = acc[mt][nt][0], v1 = acc[mt][nt][1];
            float v2 = acc[mt][nt][2], v3 = acc[mt][nt][3];
            if (RELU) {
                v0 = fmaxf(v0, 0.f); v1 = fmaxf(v1, 0.f);
                v2 = fmaxf(v2, 0.f); v3 = fmaxf(v3, 0.f);
            }
            if (SPLIT == 0) {
                *(float2*)(C + (size_t)r0 * N + col) = make_float2(v0, v1);
                *(float2*)(C + (size_t)(r0 + 8) * N + col) = make_float2(v2, v3);
            } else {
                uint32_t h, l;
                split2(v0, v1, h, l);
                *(uint32_t*)(Ch + (size_t)r0 * N + col) = h;
                *(uint32_t*)(Cl + (size_t)r0 * N + col) = l;
                split2(v2, v3, h, l);
                *(uint32_t*)(Ch + (size_t)(r0 + 8) * N + col) = h;
                *(uint32_t*)(Cl + (size_t)(r0 + 8) * N + col) = l;
            }
        }
    }
}

template <int RELU, int SPLIT, int TERMS, int NSWAP, int BMT>
__global__ __launch_bounds__(256, 2)
void hgemm_kernel(const hf* __restrict__ Ah, const hf* __restrict__ Al,
                  const hf* __restrict__ Bh, const hf* __restrict__ Bl,
                  float* __restrict__ C, hf* __restrict__ Ch, hf* __restrict__ Cl,
                  int M, int N, int K) {
    int m0 = (NSWAP ? blockIdx.x : blockIdx.y) * BMT;
    int n0 = (NSWAP ? blockIdx.y : blockIdx.x) * 128;
    hgemm_body<RELU, SPLIT, TERMS, BMT>(Ah, Al, Bh, Bl, C, Ch, Cl, M, N, K, m0, n0);
}

__global__ __launch_bounds__(256, 2)
void hgemm_qkv(const hf* __restrict__ Ah, const hf* __restrict__ Al,
               const hf* __restrict__ B0h, const hf* __restrict__ B0l,
               const hf* __restrict__ B1h, const hf* __restrict__ B1l,
               const hf* __restrict__ B2h, const hf* __restrict__ B2l,
               hf* __restrict__ C0h, hf* __restrict__ C0l,
               hf* __restrict__ C1h, hf* __restrict__ C1l,
               hf* __restrict__ C2h, hf* __restrict__ C2l,
               int M, int N, int K) {
    const hf* Bh = (blockIdx.z == 0) ? B0h : (blockIdx.z == 1) ? B1h : B2h;
    const hf* Bl = (blockIdx.z == 0) ? B0l : (blockIdx.z == 1) ? B1l : B2l;
    hf* Ch = (blockIdx.z == 0) ? C0h : (blockIdx.z == 1) ? C1h : C2h;
    hf* Cl = (blockIdx.z == 0) ? C0l : (blockIdx.z == 1) ? C1l : C2l;
    hgemm_body<0, 1, 3, 128>(Ah, Al, Bh, Bl, nullptr, Ch, Cl, M, N, K,
                             blockIdx.y * 128, blockIdx.x * 128);
}

#define GS3_128 (2 * (4 * 128 * 80))               // 81920
#define GS3_64  (2 * (2 * 64 * 80 + 2 * 128 * 80)) // 61440
#define GS1_128 (2 * (2 * 128 * 80))               // 40960

// ---------------------------------------------------------------------------
// ALL weight transposes + fp16 hi/lo splits for all layers in ONE launch.
// ---------------------------------------------------------------------------
__global__ __launch_bounds__(256)
void wconv_all(const float* __restrict__ ffw, const float* __restrict__ qw,
               const float* __restrict__ kw, const float* __restrict__ vw,
               const float* __restrict__ ow,
               hf* __restrict__ ffth, hf* __restrict__ fftl,
               hf* __restrict__ qth,  hf* __restrict__ qtl,
               hf* __restrict__ kth,  hf* __restrict__ ktl,
               hf* __restrict__ vth,  hf* __restrict__ vtl,
               hf* __restrict__ oth,  hf* __restrict__ otl) {
    __shared__ float t[32][33];
    int layer = blockIdx.y;
    int b = blockIdx.x;

    const float* W; hf* Th; hf* Tl; int R, Cc, tt;
    if (b < 4096)      { W = ffw + (size_t)layer * EDIM * FDIM;
                         Th = ffth + (size_t)layer * FDIM * EDIM;
                         Tl = fftl + (size_t)layer * FDIM * EDIM;
                         R = EDIM; Cc = FDIM; tt = b; }
    else if (b < 8192) { W = qw + (size_t)layer * FDIM * HDW;
                         Th = qth + (size_t)layer * HDW * FDIM;
                         Tl = qtl + (size_t)layer * HDW * FDIM;
                         R = FDIM; Cc = HDW; tt = b - 4096; }
    else if (b < 12288){ W = kw + (size_t)layer * FDIM * HDW;
                         Th = kth + (size_t)layer * HDW * FDIM;
                         Tl = ktl + (size_t)layer * HDW * FDIM;
                         R = FDIM; Cc = HDW; tt = b - 8192; }
    else if (b < 16384){ W = vw + (size_t)layer * FDIM * HDW;
                         Th = vth + (size_t)layer * HDW * FDIM;
                         Tl = vtl + (size_t)layer * HDW * FDIM;
                         R = FDIM; Cc = HDW; tt = b - 12288; }
    else               { W = ow + (size_t)layer * HDW * EDIM;
                         Th = oth + (size_t)layer * EDIM * HDW;
                         Tl = otl + (size_t)layer * EDIM * HDW;
                         R = HDW; Cc = EDIM; tt = b - 16384; }

    int ntx = Cc / 32;
    int c0 = (tt % ntx) * 32, r0 = (tt / ntx) * 32;
    int tx = threadIdx.x & 31, ty = threadIdx.x >> 5;
#pragma unroll
    for (int i = 0; i < 32; i += 8)
        t[ty + i][tx] = W[(size_t)(r0 + ty + i) * Cc + c0 + tx];
    __syncthreads();
#pragma unroll
    for (int i = 0; i < 32; i += 8) {
        float v = t[tx][ty + i];
        hf h = __float2half_rn(v);
        hf l = __float2half_rn(v - __half2float(h));
        size_t o = (size_t)(c0 + ty + i) * R + r0 + tx;
        Th[o] = h;
        Tl[o] = l;
    }
}

// hi-only fp16 conversion (embedding matrix for 1-term logits)
__global__ __launch_bounds__(256)
void conv_h(const float* __restrict__ X, hf* __restrict__ Xh, int n4) {
    int i = blockIdx.x * 256 + threadIdx.x;
    if (i >= n4) return;
    float4 v = ((const float4*)X)[i];
    uint32_t h0 = pk(__float2half_rn(v.x), __float2half_rn(v.y));
    uint32_t h1 = pk(__float2half_rn(v.z), __float2half_rn(v.w));
    ((uint2*)Xh)[i] = make_uint2(h0, h1);
}

__global__ void embed_kernel(const int* __restrict__ x,
                             const float* __restrict__ emb,
                             hf* __restrict__ hh, hf* __restrict__ hl) {
    int s = blockIdx.x;
    int tok = x[s];
    const float4* src = (const float4*)(emb + (size_t)tok * EDIM);
    uint2* dh = (uint2*)(hh + (size_t)s * EDIM);
    uint2* dl = (uint2*)(hl + (size_t)s * EDIM);
    for (int i = threadIdx.x; i < EDIM / 4; i += blockDim.x) {
        float4 v = src[i];
        uint32_t h0, l0, h1, l1;
        split2(v.x, v.y, h0, l0);
        split2(v.z, v.w, h1, l1);
        dh[i] = make_uint2(h0, h1);
        dl[i] = make_uint2(l0, l1);
    }
}

// ---------------------------------------------------------------------------
// Flash attention, split-KV (2 halves). Q kept in DEDICATED smem (fragments
// reloaded per tile via ldmatrix) to cut register pressure; KV 2-stage.
// ---------------------------------------------------------------------------
#define KP    272
#define QPL   (128 * KP)             // 34816 per Q plane
#define QREG  (2 * QPL)              // 69632
#define APL   (64 * KP)              // 17408 per KV plane
#define ASTG4 (4 * APL)              // 69632 per KV stage
#define ATT_SMEM (QREG + 2 * ASTG4)  // 208896

__global__ __launch_bounds__(256)
void attn_mma(const hf* __restrict__ Qh, const hf* __restrict__ Ql,
              const hf* __restrict__ Kh, const hf* __restrict__ Kl,
              const hf* __restrict__ Vh, const hf* __restrict__ Vl,
              float* __restrict__ opart, float* __restrict__ gm,
              float* __restrict__ gl) {
    extern __shared__ char smraw[];
    uint32_t sb = smem_u32(smraw);
    uint32_t kvb = sb + QREG;
    const int tid = threadIdx.x, lane = tid & 31, warp = tid >> 5;
    const int lq = lane >> 2, lr = lane & 3;
    const int qb = (SQ / 128 - 1) - blockIdx.x;   // descending: big CTAs first
    const int head = blockIdx.y;
    const int half = blockIdx.z;

    const int T0 = (half == 0) ? 0 : qb + 1;
    const int NT = qb + 1;

    // Q load into dedicated smem region
    {
        const hf* qsrc[2] = { Qh, Ql };
#pragma unroll
        for (int pl = 0; pl < 2; pl++)
#pragma unroll
            for (int u = 0; u < 8; u++) {
                int id = tid + u * 256;
                int row = id >> 4, c = id & 15;
                cp_async16(sb + pl * QPL + row * KP + c * 16,
                           qsrc[pl] + (size_t)(qb * 128 + row) * HDW + head * HD + c * 8);
            }
        cp_commit();
    }

    const hf* kvsrc[4] = { Kh, Kl, Vh, Vl };
    auto loadKV = [&](int t, int st) {
        uint32_t base = kvb + (uint32_t)st * ASTG4;
#pragma unroll
        for (int pl = 0; pl < 4; pl++)
#pragma unroll
            for (int u = 0; u < 4; u++) {
                int id = tid + u * 256;
                int row = id >> 4, c = id & 15;
                cp_async16(base + pl * APL + row * KP + c * 16,
                           kvsrc[pl] + (size_t)(t * 64 + row) * HDW + head * HD + c * 8);
            }
        cp_commit();
    };

    float o_acc[16][4];
#pragma unroll
    for (int i = 0; i < 16; i++)
#pragma unroll
        for (int j = 0; j < 4; j++) o_acc[i][j] = 0.f;
    float mrun[2] = { -1e30f, -1e30f };
    float lrun[2] = { 0.f, 0.f };

    loadKV(T0, 0);
    if (NT > 1) loadKV(T0 + 1, 1);

    const uint32_t q_off = (uint32_t)(warp * 16 + (lane & 15)) * KP +
                           (uint32_t)(((lane >> 4) & 1) * 16);
    const uint32_t k_off = (uint32_t)(((lane >> 4) & 1) * 8 + (lane & 7)) * KP +
                           (uint32_t)(((lane >> 3) & 1) * 16);
    const uint32_t v_off = (uint32_t)(((lane >> 3) & 1) * 8 + (lane & 7)) * KP +
                           (uint32_t)(((lane >> 4) & 1) * 16);

    for (int tt = 0; tt < NT; tt++) {
        const int t = T0 + tt;
        // last tile must drain ALL groups (fixes NT==1 under-wait -> NaN)
        if (tt + 1 < NT) cp_wait<1>(); else cp_wait<0>();
        __syncthreads();

        uint32_t stg = kvb + (uint32_t)(tt & 1) * ASTG4;

        float s_acc[8][4];
#pragma unroll
        for (int i = 0; i < 8; i++)
#pragma unroll
            for (int j = 0; j < 4; j++) s_acc[i][j] = 0.f;

#pragma unroll
        for (int kc = 0; kc < 8; kc++) {
            uint32_t qfh[4], qfl[4];
            ldsm4(qfh, sb + q_off + kc * 32);
            ldsm4(qfl, sb + QPL + q_off + kc * 32);
            uint32_t kbh[4][4], kbl[4][4];
#pragma unroll
            for (int pr = 0; pr < 4; pr++) {
                uint32_t ad = stg + k_off + pr * (16 * KP) + kc * 32;
                ldsm4(kbh[pr], ad);
                ldsm4(kbl[pr], ad + APL);
            }
#pragma unroll
            for (int pr = 0; pr < 4; pr++)
#pragma unroll
                for (int oc = 0; oc < 2; oc++) {
                    int nt = pr * 2 + oc;
                    mma16(s_acc[nt], qfh, kbh[pr][2*oc], kbh[pr][2*oc+1]);
                    mma16(s_acc[nt], qfh, kbl[pr][2*oc], kbl[pr][2*oc+1]);
                    mma16(s_acc[nt], qfl, kbh[pr][2*oc], kbh[pr][2*oc+1]);
                }
        }

        if (t >= 2 * qb) {
            int rbase = qb * 128 + warp * 16 + lq;
#pragma unroll
            for (int nt = 0; nt < 8; nt++)
#pragma unroll
                for (int rr = 0; rr < 4; rr++) {
                    int col = t * 64 + nt * 8 + 2 * lr + (rr & 1);
                    int row = rbase + (rr >> 1) * 8;
                    if (col > row) s_acc[nt][rr] = -1e30f;
                }
        }

#pragma unroll
        for (int h = 0; h < 2; h++) {
            float mloc = -1e30f;
#pragma unroll
            for (int nt = 0; nt < 8; nt++) {
                mloc = fmaxf(mloc, s_acc[nt][2*h]);
                mloc = fmaxf(mloc, s_acc[nt][2*h+1]);
            }
            mloc = fmaxf(mloc, __shfl_xor_sync(0xffffffffu, mloc, 1));
            mloc = fmaxf(mloc, __shfl_xor_sync(0xffffffffu, mloc, 2));
            float mnew = fmaxf(mrun[h], mloc);
            float live = (mnew > -1e29f) ? 1.f : 0.f;   // dead-row guard
            float corr = __expf(mrun[h] - mnew);
            mrun[h] = mnew;
            float ps = 0.f;
#pragma unroll
            for (int nt = 0; nt < 8; nt++) {
                float p0 = live * __expf(s_acc[nt][2*h]   - mnew);
                float p1 = live * __expf(s_acc[nt][2*h+1] - mnew);
                s_acc[nt][2*h] = p0;
                s_acc[nt][2*h+1] = p1;
                ps += p0 + p1;
            }
            ps += __shfl_xor_sync(0xffffffffu, ps, 1);
            ps += __shfl_xor_sync(0xffffffffu, ps, 2);
            lrun[h] = lrun[h] * corr + ps;
#pragma unroll
            for (int nt = 0; nt < 16; nt++) {
                o_acc[nt][2*h]   *= corr;
                o_acc[nt][2*h+1] *= corr;
            }
        }

#pragma unroll
        for (int kc2 = 0; kc2 < 4; kc2++) {
            uint32_t ph[4], pl[4];
            split2(s_acc[2*kc2][0],   s_acc[2*kc2][1],   ph[0], pl[0]);
            split2(s_acc[2*kc2][2],   s_acc[2*kc2][3],   ph[1], pl[1]);
            split2(s_acc[2*kc2+1][0], s_acc[2*kc2+1][1], ph[2], pl[2]);
            split2(s_acc[2*kc2+1][2], s_acc[2*kc2+1][3], ph[3], pl[3]);
#pragma unroll
            for (int dp = 0; dp < 8; dp++) {
                uint32_t vbh[4], vbl[4];
                uint32_t ad = stg + 2 * APL + v_off + kc2 * (16 * KP) + dp * 32;
                ldsm4t(vbh, ad);
                ldsm4t(vbl, ad + APL);
#pragma unroll
                for (int oc = 0; oc < 2; oc++) {
                    int nt = dp * 2 + oc;
                    mma16(o_acc[nt], ph, vbh[2*oc], vbh[2*oc+1]);
                    mma16(o_acc[nt], ph, vbl[2*oc], vbl[2*oc+1]);
                    mma16(o_acc[nt], pl, vbh[2*oc], vbh[2*oc+1]);
                }
            }
        }

        __syncthreads();            // stage (tt&1) fully consumed
        if (tt + 2 < NT) loadKV(T0 + tt + 2, tt & 1);
        else cp_commit();
    }

    // epilogue: write UNnormalized partials + (m, l)
    float* op = opart + (size_t)half * SQ * HDW;
    int r0 = qb * 128 + warp * 16 + lq;
#pragma unroll
    for (int nt = 0; nt < 16; nt++) {
        int col = head * HD + nt * 8 + 2 * lr;
        *(float2*)(op + (size_t)r0 * HDW + col) =
            make_float2(o_acc[nt][0], o_acc[nt][1]);
        *(float2*)(op + (size_t)(r0 + 8) * HDW + col) =
            make_float2(o_acc[nt][2], o_acc[nt][3]);
    }
    if (lr == 0) {
        int base = half * NH * SQ + head * SQ;
        gm[base + r0] = mrun[0];
        gl[base + r0] = lrun[0];
        gm[base + r0 + 8] = mrun[1];
        gl[base + r0 + 8] = lrun[1];
    }
}

// merge the two KV halves; write fp16 hi/lo planes of O
__global__ __launch_bounds__(256)
void attn_merge(const float* __restrict__ opart, const float* __restrict__ gm,
                const float* __restrict__ gl,
                hf* __restrict__ Oh, hf* __restrict__ Ol) {
    int row = blockIdx.x;
    int head = threadIdx.x >> 5;
    int lane = threadIdx.x & 31;

    int base = head * SQ + row;
    float m0 = gm[base],          m1 = gm[NH * SQ + base];
    float l0 = gl[base],          l1 = gl[NH * SQ + base];
    float mx = fmaxf(m0, m1);
    float e0 = __expf(m0 - mx), e1 = __expf(m1 - mx);
    float inv = 1.f / (l0 * e0 + l1 * e1);

    size_t off = (size_t)row * HDW + head * HD + lane * 4;
    float4 a = *(const float4*)(opart + off);
    float4 b = *(const float4*)(opart + (size_t)SQ * HDW + off);
    float o0 = (e0 * a.x + e1 * b.x) * inv;
    float o1 = (e0 * a.y + e1 * b.y) * inv;
    float o2 = (e0 * a.z + e1 * b.z) * inv;
    float o3 = (e0 * a.w + e1 * b.w) * inv;

    uint32_t h, l;
    split2(o0, o1, h, l);
    *(uint32_t*)(Oh + off) = h;
    *(uint32_t*)(Ol + off) = l;
    split2(o2, o3, h, l);
    *(uint32_t*)(Oh + off + 2) = h;
    *(uint32_t*)(Ol + off + 2) = l;
}

// ---------------------------------------------------------------------------
extern "C" void kernel_launch(void* const* d_in, const int* in_sizes, int n_in,
                              void* d_out, int out_size) {
    const int*   x   = (const int*)d_in[0];
    const float* emb = (const float*)d_in[1];
    const float* ffw = (const float*)d_in[2];
    const float* qw  = (const float*)d_in[3];
    const float* kw  = (const float*)d_in[4];
    const float* vw  = (const float*)d_in[5];
    const float* ow  = (const float*)d_in[6];
    float* out = (float*)d_out;

    hf *hh, *hl, *hfh, *hfl, *qh, *ql, *kh, *kl, *vh, *vl, *oh, *ol;
    hf *ffth, *fftl, *qth, *qtl, *kth, *ktl, *vth, *vtl, *oth, *otl, *eth;
    float *opart, *gmM, *gmL;
    cudaGetSymbolAddress((void**)&hh,  g_hh);  cudaGetSymbolAddress((void**)&hl,  g_hl);
    cudaGetSymbolAddress((void**)&hfh, g_hfh); cudaGetSymbolAddress((void**)&hfl, g_hfl);
    cudaGetSymbolAddress((void**)&qh,  g_qh);  cudaGetSymbolAddress((void**)&ql,  g_ql);
    cudaGetSymbolAddress((void**)&kh,  g_kh);  cudaGetSymbolAddress((void**)&kl,  g_kl);
    cudaGetSymbolAddress((void**)&vh,  g_vh);  cudaGetSymbolAddress((void**)&vl,  g_vl);
    cudaGetSymbolAddress((void**)&oh,  g_oh);  cudaGetSymbolAddress((void**)&ol,  g_ol);
    cudaGetSymbolAddress((void**)&ffth, g_ffth); cudaGetSymbolAddress((void**)&fftl, g_fftl);
    cudaGetSymbolAddress((void**)&qth,  g_qth);  cudaGetSymbolAddress((void**)&qtl,  g_qtl);
    cudaGetSymbolAddress((void**)&kth,  g_kth);  cudaGetSymbolAddress((void**)&ktl,  g_ktl);
    cudaGetSymbolAddress((void**)&vth,  g_vth);  cudaGetSymbolAddress((void**)&vtl,  g_vtl);
    cudaGetSymbolAddress((void**)&oth,  g_oth);  cudaGetSymbolAddress((void**)&otl,  g_otl);
    cudaGetSymbolAddress((void**)&eth,  g_eth);
    cudaGetSymbolAddress((void**)&opart, g_opart);
    cudaGetSymbolAddress((void**)&gmM,   g_gm);
    cudaGetSymbolAddress((void**)&gmL,   g_gl);

    cudaFuncSetAttribute(attn_mma,
                         cudaFuncAttributeMaxDynamicSharedMemorySize, ATT_SMEM);
    cudaFuncSetAttribute(hgemm_kernel<1, 1, 3, 0, 128>,
                         cudaFuncAttributeMaxDynamicSharedMemorySize, GS3_128);
    cudaFuncSetAttribute(hgemm_kernel<0, 1, 3, 0, 64>,
                         cudaFuncAttributeMaxDynamicSharedMemorySize, GS3_64);
    cudaFuncSetAttribute(hgemm_kernel<0, 0, 1, 1, 128>,
                         cudaFuncAttributeMaxDynamicSharedMemorySize, GS1_128);
    cudaFuncSetAttribute(hgemm_qkv,
                         cudaFuncAttributeMaxDynamicSharedMemorySize, GS3_128);

    embed_kernel<<<SQ, 256>>>(x, emb, hh, hl);
    conv_h<<<(VOC * EDIM / 4 + 255) / 256, 256>>>(emb, eth, VOC * EDIM / 4);
    wconv_all<<<dim3(17408, NL), 256>>>(ffw, qw, kw, vw, ow,
                                        ffth, fftl, qth, qtl, kth, ktl,
                                        vth, vtl, oth, otl);

    for (int i = 0; i < NL; i++) {
        hf* ffthi = ffth + (size_t)i * FDIM * EDIM;
        hf* fftli = fftl + (size_t)i * FDIM * EDIM;
        hf* qthi  = qth  + (size_t)i * HDW * FDIM;
        hf* qtli  = qtl  + (size_t)i * HDW * FDIM;
        hf* kthi  = kth  + (size_t)i * HDW * FDIM;
        hf* ktli  = ktl  + (size_t)i * HDW * FDIM;
        hf* vthi  = vth  + (size_t)i * HDW * FDIM;
        hf* vtli  = vtl  + (size_t)i * HDW * FDIM;
        hf* othi  = oth  + (size_t)i * EDIM * HDW;
        hf* otli  = otl  + (size_t)i * EDIM * HDW;

        // hf = relu(h @ ff_w): 3-term  (512 CTAs)
        hgemm_kernel<1, 1, 3, 0, 128><<<dim3(FDIM / 128, SQ / 128), 256, GS3_128>>>(
            hh, hl, ffthi, fftli, nullptr, hfh, hfl, SQ, FDIM, EDIM);

        // q,k,v = hf @ w: 3-term  (384 CTAs)
        hgemm_qkv<<<dim3(HDW / 128, SQ / 128, 3), 256, GS3_128>>>(
            hfh, hfl, qthi, qtli, kthi, ktli, vthi, vtli,
            qh, ql, kh, kl, vh, vl, SQ, HDW, FDIM);

        // attention: split-KV (256 balanced CTAs) + merge
        attn_mma<<<dim3(SQ / 128, NH, 2), 256, ATT_SMEM>>>(
            qh, ql, kh, kl, vh, vl, opart, gmM, gmL);
        attn_merge<<<SQ, 256>>>(opart, gmM, gmL, oh, ol);

        // h = o @ o_w: 3-term, 64-row tiles  (256 CTAs)
        hgemm_kernel<0, 1, 3, 0, 64><<<dim3(EDIM / 128, SQ / 64), 256, GS3_64>>>(
            oh, ol, othi, otli, nullptr, hh, hl, SQ, EDIM, HDW);
    }

    // logits = h @ emb^T: 1-term (pure fp16), grid swapped for B-tile L2 reuse
    hgemm_kernel<0, 0, 1, 1, 128><<<dim3(SQ / 128, VOC / 128), 256, GS1_128>>>(
        hh, hl, eth, nullptr, out, nullptr, nullptr, SQ, VOC, EDIM);
}

// round 16
// speedup vs baseline: 1.4507x; 1.0330x over previous
#include <cuda_runtime.h>
#include <cuda_fp16.h>
#include <cstdint>

#define SQ   2048
#define EDIM 1024
#define FDIM 4096
#define NH   8
#define HD   128
#define NL   4
#define VOC  32000
#define HDW  (NH * HD)     // 1024

typedef __half hf;

// ---------------------------------------------------------------------------
// static scratch: fp16 hi/lo planes
// ---------------------------------------------------------------------------
__device__ hf g_hh [SQ * EDIM];
__device__ hf g_hl [SQ * EDIM];
__device__ hf g_hfh[SQ * FDIM];
__device__ hf g_hfl[SQ * FDIM];
__device__ hf g_qh [SQ * HDW];
__device__ hf g_ql [SQ * HDW];
__device__ hf g_kh [SQ * HDW];
__device__ hf g_kl [SQ * HDW];
__device__ hf g_vh [SQ * HDW];
__device__ hf g_vl [SQ * HDW];
__device__ hf g_oh [SQ * HDW];
__device__ hf g_ol [SQ * HDW];
__device__ hf g_ffth[NL * FDIM * EDIM];
__device__ hf g_fftl[NL * FDIM * EDIM];
__device__ hf g_qth [NL * HDW * FDIM];
__device__ hf g_qtl [NL * HDW * FDIM];
__device__ hf g_kth [NL * HDW * FDIM];
__device__ hf g_ktl [NL * HDW * FDIM];
__device__ hf g_vth [NL * HDW * FDIM];
__device__ hf g_vtl [NL * HDW * FDIM];
__device__ hf g_oth [NL * EDIM * HDW];
__device__ hf g_otl [NL * EDIM * HDW];
__device__ hf g_eth [VOC * EDIM];
// attention split-KV partials
__device__ float g_opart[2 * SQ * HDW];
__device__ float g_gm  [2 * NH * SQ];
__device__ float g_gl  [2 * NH * SQ];

// ---------------------------------------------------------------------------
// helpers
// ---------------------------------------------------------------------------
__device__ __forceinline__ uint32_t smem_u32(const void* p) {
    return (uint32_t)__cvta_generic_to_shared(p);
}
__device__ __forceinline__ void cp_async16(uint32_t dst, const void* src) {
    asm volatile("cp.async.cg.shared.global [%0], [%1], 16;\n" :: "r"(dst), "l"(src));
}
__device__ __forceinline__ void cp_commit() {
    asm volatile("cp.async.commit_group;\n");
}
template <int N>
__device__ __forceinline__ void cp_wait() {
    asm volatile("cp.async.wait_group %0;\n" :: "n"(N));
}
__device__ __forceinline__ void mma16(float* c, const uint32_t* a, uint32_t b0, uint32_t b1) {
    asm volatile(
        "mma.sync.aligned.m16n8k16.row.col.f32.f16.f16.f32 "
        "{%0,%1,%2,%3}, {%4,%5,%6,%7}, {%8,%9}, {%0,%1,%2,%3};\n"
        : "+f"(c[0]), "+f"(c[1]), "+f"(c[2]), "+f"(c[3])
        : "r"(a[0]), "r"(a[1]), "r"(a[2]), "r"(a[3]), "r"(b0), "r"(b1));
}
__device__ __forceinline__ void ldsm4(uint32_t* r, uint32_t a) {
    asm volatile("ldmatrix.sync.aligned.m8n8.x4.shared.b16 {%0,%1,%2,%3}, [%4];"
                 : "=r"(r[0]), "=r"(r[1]), "=r"(r[2]), "=r"(r[3]) : "r"(a));
}
__device__ __forceinline__ void ldsm4t(uint32_t* r, uint32_t a) {
    asm volatile("ldmatrix.sync.aligned.m8n8.x4.trans.shared.b16 {%0,%1,%2,%3}, [%4];"
                 : "=r"(r[0]), "=r"(r[1]), "=r"(r[2]), "=r"(r[3]) : "r"(a));
}
__device__ __forceinline__ uint32_t pk(hf a, hf b) {
    return ((uint32_t)__half_as_ushort(b) << 16) | __half_as_ushort(a);
}
__device__ __forceinline__ void split2(float f0, float f1, uint32_t& h, uint32_t& l) {
    hf h0 = __float2half_rn(f0), h1 = __float2half_rn(f1);
    hf l0 = __float2half_rn(f0 - __half2float(h0));
    hf l1 = __float2half_rn(f1 - __half2float(h1));
    h = pk(h0, h1);
    l = pk(l0, l1);
}

// ---------------------------------------------------------------------------
// fp16 split GEMM: C[M,N] = op(A @ B^T); A[M,K], B[N,K] hi/lo half planes.
// CTA BMT x 128, BK=32, 8 warps (2x4), warp tile (BMT/2)x32, 2-stage,
// 2 CTAs/SM. TERMS=3: AhBh+AhBl+AlBh; TERMS=2: +AlBh only; TERMS=1: AhBh.
// ---------------------------------------------------------------------------
template <int RELU, int SPLIT, int TERMS, int BMT>
__device__ __forceinline__ void hgemm_body(
    const hf* __restrict__ Ah_, const hf* __restrict__ Al_,
    const hf* __restrict__ Bh_, const hf* __restrict__ Bl_,
    float* __restrict__ C, hf* __restrict__ Ch, hf* __restrict__ Cl,
    int M, int N, int K, int m0, int n0)
{
    constexpr int PLA = BMT * 80;
    constexpr int PLB = 128 * 80;
    constexpr int NAP = (TERMS == 1) ? 1 : 2;
    constexpr int NBP = (TERMS == 3) ? 2 : 1;
    constexpr int STG = NAP * PLA + NBP * PLB;
    constexpr int ACH = NAP * BMT * 4;                 // A 16B chunks / stage
    constexpr int BCH = NBP * 128 * 4;
    constexpr int CU  = (ACH + BCH) / 256;
    constexpr int WM  = BMT / 2;
    constexpr int MT  = WM / 16;

    extern __shared__ char smraw[];
    uint32_t sb = smem_u32(smraw);
    const int tid = threadIdx.x, lane = tid & 31, warp = tid >> 5;
    const int wr = warp >> 2, wc = warp & 3;
    const int lq = lane >> 2, lr = lane & 3;

    const hf* srcA[2] = { Ah_ + (size_t)m0 * K,
                          (NAP == 2) ? Al_ + (size_t)m0 * K : Ah_ };
    const hf* srcB[2] = { Bh_ + (size_t)n0 * K,
                          (NBP == 2) ? Bl_ + (size_t)n0 * K : Bh_ };

    auto issue = [&](int st, int k0) {
        uint32_t base = sb + (uint32_t)st * STG;
#pragma unroll
        for (int u = 0; u < CU; u++) {
            int id = tid + u * 256;
            if (id < ACH) {
                int pl = id / (BMT * 4), rem = id % (BMT * 4);
                int row = rem >> 2, c = rem & 3;
                cp_async16(base + pl * PLA + row * 80 + c * 16,
                           srcA[pl] + (size_t)row * K + k0 + c * 8);
            } else {
                int id2 = id - ACH;
                int pl = id2 >> 9, rem = id2 & 511;
                int row = rem >> 2, c = rem & 3;
                cp_async16(base + NAP * PLA + pl * PLB + row * 80 + c * 16,
                           srcB[pl] + (size_t)row * K + k0 + c * 8);
            }
        }
        cp_commit();
    };

    const uint32_t a_off = (uint32_t)(wr * WM + (lane & 15)) * 80 +
                           (uint32_t)(((lane >> 4) & 1) * 16);
    const uint32_t b_off = (uint32_t)(wc * 32 + ((lane >> 4) & 1) * 8 + (lane & 7)) * 80 +
                           (uint32_t)(((lane >> 3) & 1) * 16);

    float acc[MT][4][4];
#pragma unroll
    for (int i = 0; i < MT; i++)
#pragma unroll
        for (int j = 0; j < 4; j++)
#pragma unroll
            for (int q = 0; q < 4; q++) acc[i][j][q] = 0.f;

    const int KT = K >> 5;
    issue(0, 0);
    issue(1, 32);

    for (int kt = 0; kt < KT; kt++) {
        if (kt + 1 < KT) cp_wait<1>(); else cp_wait<0>();
        __syncthreads();

        uint32_t stg = sb + (uint32_t)(kt & 1) * STG;
#pragma unroll
        for (int ks = 0; ks < 2; ks++) {
            uint32_t ah[MT][4], al[MT][4];
#pragma unroll
            for (int mt = 0; mt < MT; mt++) {
                uint32_t ad = stg + a_off + mt * (16 * 80) + ks * 32;
                ldsm4(ah[mt], ad);
                if (TERMS >= 2) ldsm4(al[mt], ad + PLA);
            }
            uint32_t bh[2][4], bl[2][4];
#pragma unroll
            for (int pr = 0; pr < 2; pr++) {
                uint32_t bd = stg + NAP * PLA + b_off + pr * (16 * 80) + ks * 32;
                ldsm4(bh[pr], bd);
                if (TERMS == 3) ldsm4(bl[pr], bd + PLB);
            }
#pragma unroll
            for (int mt = 0; mt < MT; mt++)
#pragma unroll
                for (int pr = 0; pr < 2; pr++)
#pragma unroll
                    for (int oc = 0; oc < 2; oc++) {
                        int nt = pr * 2 + oc;
                        mma16(acc[mt][nt], ah[mt], bh[pr][2*oc], bh[pr][2*oc+1]);
                        if (TERMS == 3)
                            mma16(acc[mt][nt], ah[mt], bl[pr][2*oc], bl[pr][2*oc+1]);
                        if (TERMS >= 2)
                            mma16(acc[mt][nt], al[mt], bh[pr][2*oc], bh[pr][2*oc+1]);
                    }
        }
        __syncthreads();
        if (kt + 2 < KT) issue(kt & 1, (kt + 2) * 32);
        else cp_commit();
    }

    // epilogue
#pragma unroll
    for (int mt = 0; mt < MT; mt++) {
        int r0 = m0 + wr * WM + mt * 16 + lq;
#pragma unroll
        for (int nt = 0; nt < 4; nt++) {
            int col = n0 + wc * 32 + nt * 8 + lr * 2;
            float v0 = acc[mt][nt][0], v1 = acc[mt][nt][1];
            float v2 = acc[mt][nt][2], v3 = acc[mt][nt][3];
            if (RELU) {
                v0 = fmaxf(v0, 0.f); v1 = fmaxf(v1, 0.f);
                v2 = fmaxf(v2, 0.f); v3 = fmaxf(v3, 0.f);
            }
            if (SPLIT == 0) {
                *(float2*)(C + (size_t)r0 * N + col) = make_float2(v0, v1);
                *(float2*)(C + (size_t)(r0 + 8) * N + col) = make_float2(v2, v3);
            } else {
                uint32_t h, l;
                split2(v0, v1, h, l);
                *(uint32_t*)(Ch + (size_t)r0 * N + col) = h;
                *(uint32_t*)(Cl + (size_t)r0 * N + col) = l;
                split2(v2, v3, h, l);
                *(uint32_t*)(Ch + (size_t)(r0 + 8) * N + col) = h;
                *(uint32_t*)(Cl + (size_t)(r0 + 8) * N + col) = l;
            }
        }
    }
}

template <int RELU, int SPLIT, int TERMS, int NSWAP, int BMT>
__global__ __launch_bounds__(256, 2)
void hgemm_kernel(const hf* __restrict__ Ah, const hf* __restrict__ Al,
                  const hf* __restrict__ Bh, const hf* __restrict__ Bl,
                  float* __restrict__ C, hf* __restrict__ Ch, hf* __restrict__ Cl,
                  int M, int N, int K) {
    int m0 = (NSWAP ? blockIdx.x : blockIdx.y) * BMT;
    int n0 = (NSWAP ? blockIdx.y : blockIdx.x) * 128;
    hgemm_body<RELU, SPLIT, TERMS, BMT>(Ah, Al, Bh, Bl, C, Ch, Cl, M, N, K, m0, n0);
}

// qkv: 64-row CTA tiles (768 CTAs) to kill wave quantization
__global__ __launch_bounds__(256, 2)
void hgemm_qkv(const hf* __restrict__ Ah, const hf* __restrict__ Al,
               const hf* __restrict__ B0h, const hf* __restrict__ B0l,
               const hf* __restrict__ B1h, const hf* __restrict__ B1l,
               const hf* __restrict__ B2h, const hf* __restrict__ B2l,
               hf* __restrict__ C0h, hf* __restrict__ C0l,
               hf* __restrict__ C1h, hf* __restrict__ C1l,
               hf* __restrict__ C2h, hf* __restrict__ C2l,
               int M, int N, int K) {
    const hf* Bh = (blockIdx.z == 0) ? B0h : (blockIdx.z == 1) ? B1h : B2h;
    const hf* Bl = (blockIdx.z == 0) ? B0l : (blockIdx.z == 1) ? B1l : B2l;
    hf* Ch = (blockIdx.z == 0) ? C0h : (blockIdx.z == 1) ? C1h : C2h;
    hf* Cl = (blockIdx.z == 0) ? C0l : (blockIdx.z == 1) ? C1l : C2l;
    hgemm_body<0, 1, 3, 64>(Ah, Al, Bh, Bl, nullptr, Ch, Cl, M, N, K,
                            blockIdx.y * 64, blockIdx.x * 128);
}

#define GS3_128 (2 * (4 * 128 * 80))               // 81920
#define GS3_64  (2 * (2 * 64 * 80 + 2 * 128 * 80)) // 61440
#define GS1_128 (2 * (2 * 128 * 80))               // 40960

// ---------------------------------------------------------------------------
// ALL weight transposes + fp16 hi/lo splits for all layers in ONE launch.
// ---------------------------------------------------------------------------
__global__ __launch_bounds__(256)
void wconv_all(const float* __restrict__ ffw, const float* __restrict__ qw,
               const float* __restrict__ kw, const float* __restrict__ vw,
               const float* __restrict__ ow,
               hf* __restrict__ ffth, hf* __restrict__ fftl,
               hf* __restrict__ qth,  hf* __restrict__ qtl,
               hf* __restrict__ kth,  hf* __restrict__ ktl,
               hf* __restrict__ vth,  hf* __restrict__ vtl,
               hf* __restrict__ oth,  hf* __restrict__ otl) {
    __shared__ float t[32][33];
    int layer = blockIdx.y;
    int b = blockIdx.x;

    const float* W; hf* Th; hf* Tl; int R, Cc, tt;
    if (b < 4096)      { W = ffw + (size_t)layer * EDIM * FDIM;
                         Th = ffth + (size_t)layer * FDIM * EDIM;
                         Tl = fftl + (size_t)layer * FDIM * EDIM;
                         R = EDIM; Cc = FDIM; tt = b; }
    else if (b < 8192) { W = qw + (size_t)layer * FDIM * HDW;
                         Th = qth + (size_t)layer * HDW * FDIM;
                         Tl = qtl + (size_t)layer * HDW * FDIM;
                         R = FDIM; Cc = HDW; tt = b - 4096; }
    else if (b < 12288){ W = kw + (size_t)layer * FDIM * HDW;
                         Th = kth + (size_t)layer * HDW * FDIM;
                         Tl = ktl + (size_t)layer * HDW * FDIM;
                         R = FDIM; Cc = HDW; tt = b - 8192; }
    else if (b < 16384){ W = vw + (size_t)layer * FDIM * HDW;
                         Th = vth + (size_t)layer * HDW * FDIM;
                         Tl = vtl + (size_t)layer * HDW * FDIM;
                         R = FDIM; Cc = HDW; tt = b - 12288; }
    else               { W = ow + (size_t)layer * HDW * EDIM;
                         Th = oth + (size_t)layer * EDIM * HDW;
                         Tl = otl + (size_t)layer * EDIM * HDW;
                         R = HDW; Cc = EDIM; tt = b - 16384; }

    int ntx = Cc / 32;
    int c0 = (tt % ntx) * 32, r0 = (tt / ntx) * 32;
    int tx = threadIdx.x & 31, ty = threadIdx.x >> 5;
#pragma unroll
    for (int i = 0; i < 32; i += 8)
        t[ty + i][tx] = W[(size_t)(r0 + ty + i) * Cc + c0 + tx];
    __syncthreads();
#pragma unroll
    for (int i = 0; i < 32; i += 8) {
        float v = t[tx][ty + i];
        hf h = __float2half_rn(v);
        hf l = __float2half_rn(v - __half2float(h));
        size_t o = (size_t)(c0 + ty + i) * R + r0 + tx;
        Th[o] = h;
        Tl[o] = l;
    }
}

// hi-only fp16 conversion (embedding matrix for 1-term logits)
__global__ __launch_bounds__(256)
void conv_h(const float* __restrict__ X, hf* __restrict__ Xh, int n4) {
    int i = blockIdx.x * 256 + threadIdx.x;
    if (i >= n4) return;
    float4 v = ((const float4*)X)[i];
    uint32_t h0 = pk(__float2half_rn(v.x), __float2half_rn(v.y));
    uint32_t h1 = pk(__float2half_rn(v.z), __float2half_rn(v.w));
    ((uint2*)Xh)[i] = make_uint2(h0, h1);
}

__global__ void embed_kernel(const int* __restrict__ x,
                             const float* __restrict__ emb,
                             hf* __restrict__ hh, hf* __restrict__ hl) {
    int s = blockIdx.x;
    int tok = x[s];
    const float4* src = (const float4*)(emb + (size_t)tok * EDIM);
    uint2* dh = (uint2*)(hh + (size_t)s * EDIM);
    uint2* dl = (uint2*)(hl + (size_t)s * EDIM);
    for (int i = threadIdx.x; i < EDIM / 4; i += blockDim.x) {
        float4 v = src[i];
        uint32_t h0, l0, h1, l1;
        split2(v.x, v.y, h0, l0);
        split2(v.z, v.w, h1, l1);
        dh[i] = make_uint2(h0, h1);
        dl[i] = make_uint2(l0, l1);
    }
}

// ---------------------------------------------------------------------------
// Flash attention, split-KV (2 halves). Q in dedicated smem; KV 2-stage.
// ---------------------------------------------------------------------------
#define KP    272
#define QPL   (128 * KP)             // 34816 per Q plane
#define QREG  (2 * QPL)              // 69632
#define APL   (64 * KP)              // 17408 per KV plane
#define ASTG4 (4 * APL)              // 69632 per KV stage
#define ATT_SMEM (QREG + 2 * ASTG4)  // 208896

__global__ __launch_bounds__(256)
void attn_mma(const hf* __restrict__ Qh, const hf* __restrict__ Ql,
              const hf* __restrict__ Kh, const hf* __restrict__ Kl,
              const hf* __restrict__ Vh, const hf* __restrict__ Vl,
              float* __restrict__ opart, float* __restrict__ gm,
              float* __restrict__ gl) {
    extern __shared__ char smraw[];
    uint32_t sb = smem_u32(smraw);
    uint32_t kvb = sb + QREG;
    const int tid = threadIdx.x, lane = tid & 31, warp = tid >> 5;
    const int lq = lane >> 2, lr = lane & 3;
    const int qb = (SQ / 128 - 1) - blockIdx.x;   // descending: big CTAs first
    const int head = blockIdx.y;
    const int half = blockIdx.z;

    const int T0 = (half == 0) ? 0 : qb + 1;
    const int NT = qb + 1;

    // Q load into dedicated smem region
    {
        const hf* qsrc[2] = { Qh, Ql };
#pragma unroll
        for (int pl = 0; pl < 2; pl++)
#pragma unroll
            for (int u = 0; u < 8; u++) {
                int id = tid + u * 256;
                int row = id >> 4, c = id & 15;
                cp_async16(sb + pl * QPL + row * KP + c * 16,
                           qsrc[pl] + (size_t)(qb * 128 + row) * HDW + head * HD + c * 8);
            }
        cp_commit();
    }

    const hf* kvsrc[4] = { Kh, Kl, Vh, Vl };
    auto loadKV = [&](int t, int st) {
        uint32_t base = kvb + (uint32_t)st * ASTG4;
#pragma unroll
        for (int pl = 0; pl < 4; pl++)
#pragma unroll
            for (int u = 0; u < 4; u++) {
                int id = tid + u * 256;
                int row = id >> 4, c = id & 15;
                cp_async16(base + pl * APL + row * KP + c * 16,
                           kvsrc[pl] + (size_t)(t * 64 + row) * HDW + head * HD + c * 8);
            }
        cp_commit();
    };

    float o_acc[16][4];
#pragma unroll
    for (int i = 0; i < 16; i++)
#pragma unroll
        for (int j = 0; j < 4; j++) o_acc[i][j] = 0.f;
    float mrun[2] = { -1e30f, -1e30f };
    float lrun[2] = { 0.f, 0.f };

    loadKV(T0, 0);
    if (NT > 1) loadKV(T0 + 1, 1);

    const uint32_t q_off = (uint32_t)(warp * 16 + (lane & 15)) * KP +
                           (uint32_t)(((lane >> 4) & 1) * 16);
    const uint32_t k_off = (uint32_t)(((lane >> 4) & 1) * 8 + (lane & 7)) * KP +
                           (uint32_t)(((lane >> 3) & 1) * 16);
    const uint32_t v_off = (uint32_t)(((lane >> 3) & 1) * 8 + (lane & 7)) * KP +
                           (uint32_t)(((lane >> 4) & 1) * 16);

    for (int tt = 0; tt < NT; tt++) {
        const int t = T0 + tt;
        // last tile must drain ALL groups (NT==1 needs Q AND KV0)
        if (tt + 1 < NT) cp_wait<1>(); else cp_wait<0>();
        __syncthreads();

        uint32_t stg = kvb + (uint32_t)(tt & 1) * ASTG4;

        float s_acc[8][4];
#pragma unroll
        for (int i = 0; i < 8; i++)
#pragma unroll
            for (int j = 0; j < 4; j++) s_acc[i][j] = 0.f;

#pragma unroll
        for (int kc = 0; kc < 8; kc++) {
            uint32_t qfh[4], qfl[4];
            ldsm4(qfh, sb + q_off + kc * 32);
            ldsm4(qfl, sb + QPL + q_off + kc * 32);
            uint32_t kbh[4][4], kbl[4][4];
#pragma unroll
            for (int pr = 0; pr < 4; pr++) {
                uint32_t ad = stg + k_off + pr * (16 * KP) + kc * 32;
                ldsm4(kbh[pr], ad);
                ldsm4(kbl[pr], ad + APL);
            }
#pragma unroll
            for (int pr = 0; pr < 4; pr++)
#pragma unroll
                for (int oc = 0; oc < 2; oc++) {
                    int nt = pr * 2 + oc;
                    mma16(s_acc[nt], qfh, kbh[pr][2*oc], kbh[pr][2*oc+1]);
                    mma16(s_acc[nt], qfh, kbl[pr][2*oc], kbl[pr][2*oc+1]);
                    mma16(s_acc[nt], qfl, kbh[pr][2*oc], kbh[pr][2*oc+1]);
                }
        }

        if (t >= 2 * qb) {
            int rbase = qb * 128 + warp * 16 + lq;
#pragma unroll
            for (int nt = 0; nt < 8; nt++)
#pragma unroll
                for (int rr = 0; rr < 4; rr++) {
                    int col = t * 64 + nt * 8 + 2 * lr + (rr & 1);
                    int row = rbase + (rr >> 1) * 8;
                    if (col > row) s_acc[nt][rr] = -1e30f;
                }
        }

#pragma unroll
        for (int h = 0; h < 2; h++) {
            float mloc = -1e30f;
#pragma unroll
            for (int nt = 0; nt < 8; nt++) {
                mloc = fmaxf(mloc, s_acc[nt][2*h]);
                mloc = fmaxf(mloc, s_acc[nt][2*h+1]);
            }
            mloc = fmaxf(mloc, __shfl_xor_sync(0xffffffffu, mloc, 1));
            mloc = fmaxf(mloc, __shfl_xor_sync(0xffffffffu, mloc, 2));
            float mnew = fmaxf(mrun[h], mloc);
            float live = (mnew > -1e29f) ? 1.f : 0.f;   // dead-row guard
            float corr = __expf(mrun[h] - mnew);
            mrun[h] = mnew;
            float ps = 0.f;
#pragma unroll
            for (int nt = 0; nt < 8; nt++) {
                float p0 = live * __expf(s_acc[nt][2*h]   - mnew);
                float p1 = live * __expf(s_acc[nt][2*h+1] - mnew);
                s_acc[nt][2*h] = p0;
                s_acc[nt][2*h+1] = p1;
                ps += p0 + p1;
            }
            ps += __shfl_xor_sync(0xffffffffu, ps, 1);
            ps += __shfl_xor_sync(0xffffffffu, ps, 2);
            lrun[h] = lrun[h] * corr + ps;
#pragma unroll
            for (int nt = 0; nt < 16; nt++) {
                o_acc[nt][2*h]   *= corr;
                o_acc[nt][2*h+1] *= corr;
            }
        }

#pragma unroll
        for (int kc2 = 0; kc2 < 4; kc2++) {
            uint32_t ph[4], pl[4];
            split2(s_acc[2*kc2][0],   s_acc[2*kc2][1],   ph[0], pl[0]);
            split2(s_acc[2*kc2][2],   s_acc[2*kc2][3],   ph[1], pl[1]);
            split2(s_acc[2*kc2+1][0], s_acc[2*kc2+1][1], ph[2], pl[2]);
            split2(s_acc[2*kc2+1][2], s_acc[2*kc2+1][3], ph[3], pl[3]);
#pragma unroll
            for (int dp = 0; dp < 8; dp++) {
                uint32_t vbh[4], vbl[4];
                uint32_t ad = stg + 2 * APL + v_off + kc2 * (16 * KP) + dp * 32;
                ldsm4t(vbh, ad);
                ldsm4t(vbl, ad + APL);
#pragma unroll
                for (int oc = 0; oc < 2; oc++) {
                    int nt = dp * 2 + oc;
                    mma16(o_acc[nt], ph, vbh[2*oc], vbh[2*oc+1]);
                    mma16(o_acc[nt], ph, vbl[2*oc], vbl[2*oc+1]);
                    mma16(o_acc[nt], pl, vbh[2*oc], vbh[2*oc+1]);
                }
            }
        }

        __syncthreads();            // stage (tt&1) fully consumed
        if (tt + 2 < NT) loadKV(T0 + tt + 2, tt & 1);
        else cp_commit();
    }

    // epilogue: write UNnormalized partials + (m, l)
    float* op = opart + (size_t)half * SQ * HDW;
    int r0 = qb * 128 + warp * 16 + lq;
#pragma unroll
    for (int nt = 0; nt < 16; nt++) {
        int col = head * HD + nt * 8 + 2 * lr;
        *(float2*)(op + (size_t)r0 * HDW + col) =
            make_float2(o_acc[nt][0], o_acc[nt][1]);
        *(float2*)(op + (size_t)(r0 + 8) * HDW + col) =
            make_float2(o_acc[nt][2], o_acc[nt][3]);
    }
    if (lr == 0) {
        int base = half * NH * SQ + head * SQ;
        gm[base + r0] = mrun[0];
        gl[base + r0] = lrun[0];
        gm[base + r0 + 8] = mrun[1];
        gl[base + r0 + 8] = lrun[1];
    }
}

// merge the two KV halves; write fp16 hi/lo planes of O
__global__ __launch_bounds__(256)
void attn_merge(const float* __restrict__ opart, const float* __restrict__ gm,
                const float* __restrict__ gl,
                hf* __restrict__ Oh, hf* __restrict__ Ol) {
    int row = blockIdx.x;
    int head = threadIdx.x >> 5;
    int lane = threadIdx.x & 31;

    int base = head * SQ + row;
    float m0 = gm[base],          m1 = gm[NH * SQ + base];
    float l0 = gl[base],          l1 = gl[NH * SQ + base];
    float mx = fmaxf(m0, m1);
    float e0 = __expf(m0 - mx), e1 = __expf(m1 - mx);
    float inv = 1.f / (l0 * e0 + l1 * e1);

    size_t off = (size_t)row * HDW + head * HD + lane * 4;
    float4 a = *(const float4*)(opart + off);
    float4 b = *(const float4*)(opart + (size_t)SQ * HDW + off);
    float o0 = (e0 * a.x + e1 * b.x) * inv;
    float o1 = (e0 * a.y + e1 * b.y) * inv;
    float o2 = (e0 * a.z + e1 * b.z) * inv;
    float o3 = (e0 * a.w + e1 * b.w) * inv;

    uint32_t h, l;
    split2(o0, o1, h, l);
    *(uint32_t*)(Oh + off) = h;
    *(uint32_t*)(Ol + off) = l;
    split2(o2, o3, h, l);
    *(uint32_t*)(Oh + off + 2) = h;
    *(uint32_t*)(Ol + off + 2) = l;
}

// ---------------------------------------------------------------------------
extern "C" void kernel_launch(void* const* d_in, const int* in_sizes, int n_in,
                              void* d_out, int out_size) {
    const int*   x   = (const int*)d_in[0];
    const float* emb = (const float*)d_in[1];
    const float* ffw = (const float*)d_in[2];
    const float* qw  = (const float*)d_in[3];
    const float* kw  = (const float*)d_in[4];
    const float* vw  = (const float*)d_in[5];
    const float* ow  = (const float*)d_in[6];
    float* out = (float*)d_out;

    hf *hh, *hl, *hfh, *hfl, *qh, *ql, *kh, *kl, *vh, *vl, *oh, *ol;
    hf *ffth, *fftl, *qth, *qtl, *kth, *ktl, *vth, *vtl, *oth, *otl, *eth;
    float *opart, *gmM, *gmL;
    cudaGetSymbolAddress((void**)&hh,  g_hh);  cudaGetSymbolAddress((void**)&hl,  g_hl);
    cudaGetSymbolAddress((void**)&hfh, g_hfh); cudaGetSymbolAddress((void**)&hfl, g_hfl);
    cudaGetSymbolAddress((void**)&qh,  g_qh);  cudaGetSymbolAddress((void**)&ql,  g_ql);
    cudaGetSymbolAddress((void**)&kh,  g_kh);  cudaGetSymbolAddress((void**)&kl,  g_kl);
    cudaGetSymbolAddress((void**)&vh,  g_vh);  cudaGetSymbolAddress((void**)&vl,  g_vl);
    cudaGetSymbolAddress((void**)&oh,  g_oh);  cudaGetSymbolAddress((void**)&ol,  g_ol);
    cudaGetSymbolAddress((void**)&ffth, g_ffth); cudaGetSymbolAddress((void**)&fftl, g_fftl);
    cudaGetSymbolAddress((void**)&qth,  g_qth);  cudaGetSymbolAddress((void**)&qtl,  g_qtl);
    cudaGetSymbolAddress((void**)&kth,  g_kth);  cudaGetSymbolAddress((void**)&ktl,  g_ktl);
    cudaGetSymbolAddress((void**)&vth,  g_vth);  cudaGetSymbolAddress((void**)&vtl,  g_vtl);
    cudaGetSymbolAddress((void**)&oth,  g_oth);  cudaGetSymbolAddress((void**)&otl,  g_otl);
    cudaGetSymbolAddress((void**)&eth,  g_eth);
    cudaGetSymbolAddress((void**)&opart, g_opart);
    cudaGetSymbolAddress((void**)&gmM,   g_gm);
    cudaGetSymbolAddress((void**)&gmL,   g_gl);

    cudaFuncSetAttribute(attn_mma,
                         cudaFuncAttributeMaxDynamicSharedMemorySize, ATT_SMEM);
    cudaFuncSetAttribute(hgemm_kernel<1, 1, 3, 0, 128>,
                         cudaFuncAttributeMaxDynamicSharedMemorySize, GS3_128);
    cudaFuncSetAttribute(hgemm_kernel<0, 1, 3, 0, 64>,
                         cudaFuncAttributeMaxDynamicSharedMemorySize, GS3_64);
    cudaFuncSetAttribute(hgemm_kernel<0, 0, 1, 1, 128>,
                         cudaFuncAttributeMaxDynamicSharedMemorySize, GS1_128);
    cudaFuncSetAttribute(hgemm_qkv,
                         cudaFuncAttributeMaxDynamicSharedMemorySize, GS3_64);

    embed_kernel<<<SQ, 256>>>(x, emb, hh, hl);
    conv_h<<<(VOC * EDIM / 4 + 255) / 256, 256>>>(emb, eth, VOC * EDIM / 4);
    wconv_all<<<dim3(17408, NL), 256>>>(ffw, qw, kw, vw, ow,
                                        ffth, fftl, qth, qtl, kth, ktl,
                                        vth, vtl, oth, otl);

    for (int i = 0; i < NL; i++) {
        hf* ffthi = ffth + (size_t)i * FDIM * EDIM;
        hf* fftli = fftl + (size_t)i * FDIM * EDIM;
        hf* qthi  = qth  + (size_t)i * HDW * FDIM;
        hf* qtli  = qtl  + (size_t)i * HDW * FDIM;
        hf* kthi  = kth  + (size_t)i * HDW * FDIM;
        hf* ktli  = ktl  + (size_t)i * HDW * FDIM;
        hf* vthi  = vth  + (size_t)i * HDW * FDIM;
        hf* vtli  = vtl  + (size_t)i * HDW * FDIM;
        hf* othi  = oth  + (size_t)i * EDIM * HDW;
        hf* otli  = otl  + (size_t)i * EDIM * HDW;

        // hf = relu(h @ ff_w): 3-term  (512 CTAs)
        hgemm_kernel<1, 1, 3, 0, 128><<<dim3(FDIM / 128, SQ / 128), 256, GS3_128>>>(
            hh, hl, ffthi, fftli, nullptr, hfh, hfl, SQ, FDIM, EDIM);

        // q,k,v = hf @ w: 3-term, 64-row CTA tiles  (768 CTAs)
        hgemm_qkv<<<dim3(HDW / 128, SQ / 64, 3), 256, GS3_64>>>(
            hfh, hfl, qthi, qtli, kthi, ktli, vthi, vtli,
            qh, ql, kh, kl, vh, vl, SQ, HDW, FDIM);

        // attention: split-KV (256 balanced CTAs) + merge
        attn_mma<<<dim3(SQ / 128, NH, 2), 256, ATT_SMEM>>>(
            qh, ql, kh, kl, vh, vl, opart, gmM, gmL);
        attn_merge<<<SQ, 256>>>(opart, gmM, gmL, oh, ol);

        // h = o @ o_w: 3-term, 64-row tiles  (256 CTAs)
        hgemm_kernel<0, 1, 3, 0, 64><<<dim3(EDIM / 128, SQ / 64), 256, GS3_64>>>(
            oh, ol, othi, otli, nullptr, hh, hl, SQ, EDIM, HDW);
    }

    // logits = h @ emb^T: 1-term (pure fp16), grid swapped for B-tile L2 reuse
    hgemm_kernel<0, 0, 1, 1, 128><<<dim3(SQ / 128, VOC / 128), 256, GS1_128>>>(
        hh, hl, eth, nullptr, out, nullptr, nullptr, SQ, VOC, EDIM);
}